// round 3
// baseline (speedup 1.0000x reference)
#include <cuda_runtime.h>
#include <math.h>
#include <stdint.h>
#include <stddef.h>

#define NB   64
#define Hd   2048
#define G3   6144
#define TT   32
#define MELN 130
#define CHN  12
#define RHYN 3

// ---------------- device scratch (static globals; no runtime allocation) --------
__device__ float g_h[2 * NB * Hd];       // rhythm hidden ping-pong
__device__ float g_ha[2 * NB * Hd];      // melody GRU1 hidden ping-pong
__device__ float g_hb[2 * NB * Hd];      // melody GRU2 hidden ping-pong
__device__ float g_gic0[NB * G3];        // rhythm gi const (b_ih0 + z2 part)
__device__ float g_gi1z[NB * G3];        // melody gi const (b_ih1 + z1 part)
__device__ float g_gi1t[(size_t)TT * NB * G3]; // per-step gi for melody GRU1
__device__ float g_gi2[NB * G3];         // gi for melody GRU2 (per step)
__device__ float g_rlo[TT * NB * RHYN];  // rhythm log-softmax outputs
__device__ int   g_ridx[(TT + 1) * NB];  // rhythm argmax feedback (slot 0 = init)
__device__ int   g_midx[(TT + 1) * NB];  // melody argmax feedback (slot 0 = init)

// accurate-even-under-fast-math activations (expf -> __expf is still ~1e-6 rel)
__device__ __forceinline__ float sigm_f(float x) { return 1.0f / (1.0f + expf(-x)); }
__device__ __forceinline__ float tanh_f(float x) { return 1.0f - 2.0f / (expf(2.0f * x) + 1.0f); }

// ---------------- init feedback indices -----------------------------------------
__global__ void k_init_idx(int* ridx, int* midx) {
    int i = threadIdx.x;
    if (i < NB) { ridx[i] = RHYN - 1; midx[i] = MELN - 1; }
}

// ---------------- generic small matvec ------------------------------------------
// out[b][n] = act( bias[n] + sum_{k<K} x[b][k] * W[n*ldw + off + k] )
// grid (N/256, B), block 256
__global__ void k_mv(const float* __restrict__ x, int K,
                     const float* __restrict__ W, int ldw, int off,
                     const float* __restrict__ bias, int N,
                     float* __restrict__ out, int act)
{
    __shared__ float xs[128];
    int b = blockIdx.y;
    if (threadIdx.x < K) xs[threadIdx.x] = x[b * K + threadIdx.x];
    __syncthreads();
    int n = blockIdx.x * 256 + threadIdx.x;
    if (n >= N) return;
    float acc = bias[n];
    const float* wr = W + (size_t)n * ldw + off;
#pragma unroll 8
    for (int k = 0; k < K; k++) acc += xs[k] * wr[k];
    if (act) acc = tanh_f(acc);
    out[b * N + n] = acc;
}

// ---------------- fused GEMM(+GRU) step ------------------------------------------
// Computes acc[b][g*H + col] = sum_k Hin[b][k] * Whh[(g*H+col)*H + k]  (64 x 48 tile)
// plain=1: out[b*3H + g*H + col] = acc + bhh[...]
// plain=0: full GRU update ->  out[b*H + col] = h'
//   gi (if non-null) = precomputed gi; Woh/ldw_oh/idx add the one-hot column.
__global__ __launch_bounds__(256, 2)
void k_gru(const float* __restrict__ Hin,
           const float* __restrict__ Whh,
           const float* __restrict__ bhh,
           const float* __restrict__ gi,
           const float* __restrict__ Woh, int ldw_oh,
           const int* __restrict__ idx,
           float* __restrict__ out, int plain)
{
    __shared__ __align__(16) float As[32][68];   // [k][b]
    __shared__ float Bs[32][49];                 // [k][r]   r = g*16 + c
    int tid = threadIdx.x;
    int j0 = blockIdx.x * 16;
    int cx = tid & 15;        // column within gate tile
    int ry = tid >> 4;        // row group (4 b-rows)
    int lb = tid >> 2;        // 0..63 : b-row for A loads
    int lq = tid & 3;         // 0..3  : k-chunk for A loads

    float acc[4][3];
#pragma unroll
    for (int i = 0; i < 4; i++)
#pragma unroll
        for (int g = 0; g < 3; g++) acc[i][g] = 0.0f;

    for (int k0 = 0; k0 < Hd; k0 += 32) {
        float4 av0 = *(const float4*)&Hin[lb * Hd + k0 + 8 * lq];
        float4 av1 = *(const float4*)&Hin[lb * Hd + k0 + 8 * lq + 4];
        float bv[6];
#pragma unroll
        for (int l = 0; l < 6; l++) {
            int id = tid + 256 * l;
            int r = id >> 5, kk = id & 31;
            int g = r >> 4, c = r & 15;
            bv[l] = Whh[(size_t)(g * Hd + j0 + c) * Hd + k0 + kk];
        }
        __syncthreads();   // previous tile's compute done
        {
            int kbase = 8 * lq;
            As[kbase + 0][lb] = av0.x; As[kbase + 1][lb] = av0.y;
            As[kbase + 2][lb] = av0.z; As[kbase + 3][lb] = av0.w;
            As[kbase + 4][lb] = av1.x; As[kbase + 5][lb] = av1.y;
            As[kbase + 6][lb] = av1.z; As[kbase + 7][lb] = av1.w;
        }
#pragma unroll
        for (int l = 0; l < 6; l++) {
            int id = tid + 256 * l;
            int r = id >> 5, kk = id & 31;
            Bs[kk][r] = bv[l];
        }
        __syncthreads();
#pragma unroll
        for (int k = 0; k < 32; k++) {
            float4 a = *(const float4*)&As[k][ry * 4];
            float b0 = Bs[k][cx];
            float b1 = Bs[k][16 + cx];
            float b2 = Bs[k][32 + cx];
            acc[0][0] += a.x * b0; acc[0][1] += a.x * b1; acc[0][2] += a.x * b2;
            acc[1][0] += a.y * b0; acc[1][1] += a.y * b1; acc[1][2] += a.y * b2;
            acc[2][0] += a.z * b0; acc[2][1] += a.z * b1; acc[2][2] += a.z * b2;
            acc[3][0] += a.w * b0; acc[3][1] += a.w * b1; acc[3][2] += a.w * b2;
        }
    }

    int col = j0 + cx;
    if (plain) {
        float bb0 = bhh[col], bb1 = bhh[Hd + col], bb2 = bhh[2 * Hd + col];
#pragma unroll
        for (int i = 0; i < 4; i++) {
            int b = ry * 4 + i;
            out[(size_t)b * G3 + col]          = acc[i][0] + bb0;
            out[(size_t)b * G3 + Hd + col]     = acc[i][1] + bb1;
            out[(size_t)b * G3 + 2 * Hd + col] = acc[i][2] + bb2;
        }
    } else {
        float bb0 = bhh[col], bb1 = bhh[Hd + col], bb2 = bhh[2 * Hd + col];
#pragma unroll
        for (int i = 0; i < 4; i++) {
            int b = ry * 4 + i;
            float gir = gi[(size_t)b * G3 + col];
            float giz = gi[(size_t)b * G3 + Hd + col];
            float gin = gi[(size_t)b * G3 + 2 * Hd + col];
            if (Woh) {
                int ix = idx[b];
                gir += Woh[(size_t)(col) * ldw_oh + ix];
                giz += Woh[(size_t)(Hd + col) * ldw_oh + ix];
                gin += Woh[(size_t)(2 * Hd + col) * ldw_oh + ix];
            }
            float ghr = acc[i][0] + bb0;
            float ghz = acc[i][1] + bb1;
            float ghn = acc[i][2] + bb2;
            float r = sigm_f(gir + ghr);
            float u = sigm_f(giz + ghz);
            float n = tanh_f(gin + r * ghn);
            float hp = Hin[(size_t)b * Hd + col];
            out[(size_t)b * Hd + col] = (1.0f - u) * n + u * hp;
        }
    }
}

// ---------------- rhythm logits + log_softmax + argmax ---------------------------
// grid 64 (b), block 128
__global__ void k_rhylog(const float* __restrict__ Hn, const float* __restrict__ wo0,
                         const float* __restrict__ bo0,
                         float* __restrict__ rlo, int* __restrict__ ridx)
{
    int b = blockIdx.x, tid = threadIdx.x;
    float p0 = 0.f, p1 = 0.f, p2 = 0.f;
    for (int k = tid; k < Hd; k += 128) {
        float h = Hn[(size_t)b * Hd + k];
        p0 += h * wo0[k];
        p1 += h * wo0[Hd + k];
        p2 += h * wo0[2 * Hd + k];
    }
    __shared__ float s0[128], s1[128], s2[128];
    s0[tid] = p0; s1[tid] = p1; s2[tid] = p2;
    __syncthreads();
    for (int off = 64; off > 0; off >>= 1) {
        if (tid < off) {
            s0[tid] += s0[tid + off];
            s1[tid] += s1[tid + off];
            s2[tid] += s2[tid + off];
        }
        __syncthreads();
    }
    if (tid == 0) {
        float l0 = s0[0] + bo0[0], l1 = s1[0] + bo0[1], l2 = s2[0] + bo0[2];
        float m = fmaxf(l0, fmaxf(l1, l2));
        float z = m + logf(expf(l0 - m) + expf(l1 - m) + expf(l2 - m));
        rlo[b * 3 + 0] = l0 - z;
        rlo[b * 3 + 1] = l1 - z;
        rlo[b * 3 + 2] = l2 - z;
        int ix = 0; float bv = l0;
        if (l1 > bv) { bv = l1; ix = 1; }
        if (l2 > bv) { bv = l2; ix = 2; }
        ridx[b] = ix;
    }
}

// ---------------- build gi1t[t][b][:] -------------------------------------------
// grid (G3/256, TT), block 256
__global__ void k_gi1t(const float* __restrict__ gi1z,
                       const float* __restrict__ cond,   // [B, T, CH]
                       const float* __restrict__ rlo,    // [T, B, RHY]
                       const float* __restrict__ w_ih1,  // [G3, 273]
                       float* __restrict__ gi1t)
{
    int n = blockIdx.x * 256 + threadIdx.x;
    int t = blockIdx.y;
    float wr[RHYN], wc[CHN];
#pragma unroll
    for (int j = 0; j < RHYN; j++) wr[j] = w_ih1[(size_t)n * 273 + MELN + j];
#pragma unroll
    for (int j = 0; j < CHN; j++) wc[j] = w_ih1[(size_t)n * 273 + MELN + RHYN + 128 + j];
    for (int b = 0; b < NB; b++) {
        float s = gi1z[(size_t)b * G3 + n];
        const float* r = &rlo[(t * NB + b) * RHYN];
        s += r[0] * wr[0] + r[1] * wr[1] + r[2] * wr[2];
        const float* c = &cond[(b * TT + t) * CHN];
#pragma unroll
        for (int j = 0; j < CHN; j++) s += c[j] * wc[j];
        gi1t[((size_t)t * NB + b) * G3 + n] = s;
    }
}

// ---------------- melody logits + log_softmax + argmax + output ------------------
// grid 64 (b), block 256
__global__ void k_mellog(const float* __restrict__ Hn, const float* __restrict__ wo1,
                         const float* __restrict__ bo1,
                         float* __restrict__ outmel, int t, int* __restrict__ midx)
{
    __shared__ __align__(16) float hs[Hd];
    __shared__ float ls[MELN];
    __shared__ float red[256];
    int b = blockIdx.x, tid = threadIdx.x;
    for (int k = tid; k < Hd; k += 256) hs[k] = Hn[(size_t)b * Hd + k];
    __syncthreads();
    if (tid < MELN) {
        const float4* w4 = (const float4*)(wo1 + (size_t)tid * Hd);
        const float4* h4 = (const float4*)hs;
        float s = 0.f;
#pragma unroll 4
        for (int k = 0; k < Hd / 4; k++) {
            float4 a = h4[k], w = w4[k];
            s += a.x * w.x + a.y * w.y + a.z * w.z + a.w * w.w;
        }
        ls[tid] = s + bo1[tid];
    }
    __syncthreads();
    // max
    red[tid] = (tid < MELN) ? ls[tid] : -3.4e38f;
    __syncthreads();
    for (int off = 128; off > 0; off >>= 1) {
        if (tid < off) red[tid] = fmaxf(red[tid], red[tid + off]);
        __syncthreads();
    }
    float m = red[0];
    __syncthreads();
    // sum exp
    red[tid] = (tid < MELN) ? expf(ls[tid] - m) : 0.f;
    __syncthreads();
    for (int off = 128; off > 0; off >>= 1) {
        if (tid < off) red[tid] += red[tid + off];
        __syncthreads();
    }
    float z = m + logf(red[0]);
    if (tid < MELN)
        outmel[((size_t)b * TT + t) * MELN + tid] = ls[tid] - z;
    if (tid == 0) {
        int ix = 0; float bv = ls[0];
        for (int c = 1; c < MELN; c++) if (ls[c] > bv) { bv = ls[c]; ix = c; }
        midx[b] = ix;
    }
}

// ---------------- host driver ----------------------------------------------------
extern "C" void kernel_launch(void* const* d_in, const int* in_sizes, int n_in,
                              void* d_out, int out_size)
{
    const float* z1    = (const float*)d_in[0];
    const float* z2    = (const float*)d_in[1];
    const float* cond  = (const float*)d_in[2];
    const float* w_ih0 = (const float*)d_in[3];
    const float* w_hh0 = (const float*)d_in[4];
    const float* b_ih0 = (const float*)d_in[5];
    const float* b_hh0 = (const float*)d_in[6];
    const float* w_ih1 = (const float*)d_in[7];
    const float* w_hh1 = (const float*)d_in[8];
    const float* b_ih1 = (const float*)d_in[9];
    const float* b_hh1 = (const float*)d_in[10];
    const float* w_ih2 = (const float*)d_in[11];
    const float* w_hh2 = (const float*)d_in[12];
    const float* b_ih2 = (const float*)d_in[13];
    const float* b_hh2 = (const float*)d_in[14];
    const float* wi0   = (const float*)d_in[15];
    const float* bi0   = (const float*)d_in[16];
    const float* wo0   = (const float*)d_in[17];
    const float* bo0   = (const float*)d_in[18];
    const float* wi1   = (const float*)d_in[19];
    const float* bi1   = (const float*)d_in[20];
    const float* wo1   = (const float*)d_in[21];
    const float* bo1   = (const float*)d_in[22];
    float* out = (float*)d_out;

    float *hB, *haB, *hbB, *gic0, *gi1z, *gi1t, *gi2, *rlo;
    int *ridx, *midx;
    cudaGetSymbolAddress((void**)&hB,   g_h);
    cudaGetSymbolAddress((void**)&haB,  g_ha);
    cudaGetSymbolAddress((void**)&hbB,  g_hb);
    cudaGetSymbolAddress((void**)&gic0, g_gic0);
    cudaGetSymbolAddress((void**)&gi1z, g_gi1z);
    cudaGetSymbolAddress((void**)&gi1t, g_gi1t);
    cudaGetSymbolAddress((void**)&gi2,  g_gi2);
    cudaGetSymbolAddress((void**)&rlo,  g_rlo);
    cudaGetSymbolAddress((void**)&ridx, g_ridx);
    cudaGetSymbolAddress((void**)&midx, g_midx);

    float* hbuf[2]  = { hB,  hB  + NB * Hd };
    float* habuf[2] = { haB, haB + NB * Hd };
    float* hbbuf[2] = { hbB, hbB + NB * Hd };

    k_init_idx<<<1, 64>>>(ridx, midx);

    // precompute: initial hiddens + constant gi parts
    k_mv<<<dim3(Hd / 256, NB), 256>>>(z2, 128, wi0, 128, 0, bi0, Hd, hbuf[0], 1);
    k_mv<<<dim3(Hd / 256, NB), 256>>>(z1, 128, wi1, 128, 0, bi1, Hd, habuf[0], 1);
    k_mv<<<dim3(G3 / 256, NB), 256>>>(z2, 128, w_ih0, 131, RHYN, b_ih0, G3, gic0, 0);
    k_mv<<<dim3(G3 / 256, NB), 256>>>(z1, 128, w_ih1, 273, MELN + RHYN, b_ih1, G3, gi1z, 0);

    // ---- rhythm phase ----
    for (int t = 0; t < TT; t++) {
        const float* hin = hbuf[t & 1];
        float* hout = hbuf[(t + 1) & 1];
        k_gru<<<Hd / 16, 256>>>(hin, w_hh0, b_hh0, gic0, w_ih0, 131,
                                ridx + t * NB, hout, 0);
        k_rhylog<<<NB, 128>>>(hout, wo0, bo0, rlo + t * NB * RHYN, ridx + (t + 1) * NB);
    }

    // ---- precompute per-step gi for melody GRU1 ----
    k_gi1t<<<dim3(G3 / 256, TT), 256>>>(gi1z, cond, rlo, w_ih1, gi1t);

    // ---- melody phase ----
    for (int t = 0; t < TT; t++) {
        const float* haIn = habuf[t & 1];
        float* haOut = habuf[(t + 1) & 1];
        k_gru<<<Hd / 16, 256>>>(haIn, w_hh1, b_hh1, gi1t + (size_t)t * NB * G3,
                                w_ih1, 273, midx + t * NB, haOut, 0);
        // gi2 = haOut @ w_ih2^T + b_ih2  (plain GEMM)
        k_gru<<<Hd / 16, 256>>>(haOut, w_ih2, b_ih2, nullptr, nullptr, 0, nullptr,
                                gi2, 1);
        const float* hbIn = (t == 0) ? haOut : hbbuf[t & 1];
        float* hbOut = hbbuf[(t + 1) & 1];
        k_gru<<<Hd / 16, 256>>>(hbIn, w_hh2, b_hh2, gi2, nullptr, 0, nullptr,
                                hbOut, 0);
        k_mellog<<<NB, 256>>>(hbOut, wo1, bo1, out, t, midx + (t + 1) * NB);
    }
}

// round 4
// speedup vs baseline: 2.2724x; 2.2724x over previous
#include <cuda_runtime.h>
#include <cuda_bf16.h>
#include <math.h>
#include <stdint.h>
#include <stddef.h>

#define NB   64
#define Hd   2048
#define G3   6144
#define TT   32
#define MELN 130
#define CHN  12
#define RHYN 3
#define NTILE 768          // G3/8
#define K16N  128          // Hd/16
#define FRAGU32 (4*K16N*32*8)   // 131072 u32 = 512KB per H
#define BPKSZ (NTILE*K16N*32)   // uint4 count per packed weight matrix

// ---------------- device scratch ------------------------------------------------
__device__ float g_h[2 * NB * Hd];
__device__ float g_ha[2 * NB * Hd];
__device__ float g_hb[2 * NB * Hd];
__device__ float g_gic0[NB * G3];
__device__ float g_gi1z[NB * G3];
__device__ float g_gi1t[(size_t)TT * NB * G3];
__device__ float g_gi2[NB * G3];
__device__ float g_rlo[TT * NB * RHYN];
__device__ int   g_ridx[(TT + 1) * NB];
__device__ int   g_midx[(TT + 1) * NB];

__device__ uint4 g_Bp0[BPKSZ];    // packed w_hh0 (hi/lo)
__device__ uint4 g_Bp1[BPKSZ];    // packed w_hh1
__device__ uint4 g_Bp2i[BPKSZ];   // packed w_ih2
__device__ uint4 g_Bp2h[BPKSZ];   // packed w_hh2

__device__ uint32_t g_hfrag[2][FRAGU32];
__device__ uint32_t g_hafrag[2][FRAGU32];
__device__ uint32_t g_hbfrag[2][FRAGU32];

// accurate-even-under-fast-math activations
__device__ __forceinline__ float sigm_f(float x) { return 1.0f / (1.0f + expf(-x)); }
__device__ __forceinline__ float tanh_f(float x) { return 1.0f - 2.0f / (expf(2.0f * x) + 1.0f); }

__device__ __forceinline__ uint32_t packbf2(float x, float y) {
    __nv_bfloat162 v = __floats2bfloat162_rn(x, y);
    return *reinterpret_cast<uint32_t*>(&v);
}
__device__ __forceinline__ void split2(float x, float y, uint32_t& hi, uint32_t& lo) {
    __nv_bfloat16 hx = __float2bfloat16(x), hy = __float2bfloat16(y);
    float rx = x - __bfloat162float(hx);
    float ry = y - __bfloat162float(hy);
    __nv_bfloat162 H; H.x = hx; H.y = hy;
    hi = *reinterpret_cast<uint32_t*>(&H);
    lo = packbf2(rx, ry);
}

__device__ __forceinline__ void mma16816(float* d,
                                         uint32_t a0, uint32_t a1, uint32_t a2, uint32_t a3,
                                         uint32_t b0, uint32_t b1) {
    asm volatile(
        "mma.sync.aligned.m16n8k16.row.col.f32.bf16.bf16.f32 "
        "{%0,%1,%2,%3}, {%4,%5,%6,%7}, {%8,%9}, {%0,%1,%2,%3};"
        : "+f"(d[0]), "+f"(d[1]), "+f"(d[2]), "+f"(d[3])
        : "r"(a0), "r"(a1), "r"(a2), "r"(a3), "r"(b0), "r"(b1));
}

// ---------------- misc small kernels (from round 2) -----------------------------
__global__ void k_init_idx(int* ridx, int* midx) {
    int i = threadIdx.x;
    if (i < NB) { ridx[i] = RHYN - 1; midx[i] = MELN - 1; }
}

__global__ void k_mv(const float* __restrict__ x, int K,
                     const float* __restrict__ W, int ldw, int off,
                     const float* __restrict__ bias, int N,
                     float* __restrict__ out, int act)
{
    __shared__ float xs[128];
    int b = blockIdx.y;
    if (threadIdx.x < K) xs[threadIdx.x] = x[b * K + threadIdx.x];
    __syncthreads();
    int n = blockIdx.x * 256 + threadIdx.x;
    if (n >= N) return;
    float acc = bias[n];
    const float* wr = W + (size_t)n * ldw + off;
#pragma unroll 8
    for (int k = 0; k < K; k++) acc += xs[k] * wr[k];
    if (act) acc = tanh_f(acc);
    out[b * N + n] = acc;
}

// ---------------- weight packer: W[6144,2048] fp32 -> fragment-linear hi/lo ------
// out[(nt*128 + k16)*32 + lane] = {b0hi, b1hi, b0lo, b1lo}
// packed column P = nt*8 + (lane>>2); P -> (jt = P/48, g = (P%48)/16, c = P%16)
// original W row = g*2048 + jt*16 + c;  b0: k = k16*16 + 2*(lane&3) + {0,1}; b1: +8
__global__ void k_pack(const float* __restrict__ W, uint4* __restrict__ out)
{
    int id = blockIdx.x * 256 + threadIdx.x;         // 0 .. 3145727
    int l = id & 31;
    int nt = id >> 12;
    int P = nt * 8 + (l >> 2);
    int jt = P / 48, rem = P % 48;
    int g = rem >> 4, c = rem & 15;
    int k16 = (id >> 5) & 127;
    const float* wr = W + (size_t)(g * Hd + jt * 16 + c) * Hd + k16 * 16 + 2 * (l & 3);
    float x0 = wr[0], x1 = wr[1], x8 = wr[8], x9 = wr[9];
    uint32_t h01, l01, h89, l89;
    split2(x0, x1, h01, l01);
    split2(x8, x9, h89, l89);
    out[id] = make_uint4(h01, h89, l01, l89);
}

// ---------------- H fp32 -> fragment-layout hi/lo --------------------------------
// Af[((mt*128 + k16)*32 + lane)*8 + r], r0..3 = hi regs (a0..a3), r4..7 = lo regs
__global__ void k_h2frag(const float* __restrict__ H, uint32_t* __restrict__ Af)
{
    int id = blockIdx.x * 256 + threadIdx.x;         // 0 .. 16383
    int l = id & 31;
    int k16 = (id >> 5) & 127;
    int mt = id >> 12;
    int m0 = mt * 16 + (l >> 2);
    int k0 = k16 * 16 + 2 * (l & 3);
    const float* r0 = H + (size_t)m0 * Hd + k0;
    const float* r1 = H + (size_t)(m0 + 8) * Hd + k0;
    uint32_t* o = Af + (size_t)id * 8;
    uint32_t hi, lo;
    split2(r0[0], r0[1], hi, lo); o[0] = hi; o[4] = lo;   // a0
    split2(r1[0], r1[1], hi, lo); o[1] = hi; o[5] = lo;   // a1
    split2(r0[8], r0[9], hi, lo); o[2] = hi; o[6] = lo;   // a2
    split2(r1[8], r1[9], hi, lo); o[3] = hi; o[7] = lo;   // a3
}

// ---------------- tensor-core GEMM + fused GRU epilogue --------------------------
// D[64, 6144] = H[64,2048] @ W^T via 3-term bf16 split mma.
// grid = 128 (jt), block = 256 (8 warps = 4 m-tiles x 2 n-halves).
// plain=1: out[b*G3 + g*Hd + col] = D + bias
// plain=0: full GRU update; writes outH fp32 [64,Hd] and outFrag hi/lo fragments.
__global__ __launch_bounds__(256, 1)
void k_gemm(const uint4* __restrict__ Bpk,
            const uint32_t* __restrict__ Af,
            const float* __restrict__ Hfp,
            const float* __restrict__ bias,
            const float* __restrict__ gi,
            const float* __restrict__ Woh, int ldw_oh,
            const int* __restrict__ idx,
            float* __restrict__ outH,
            uint32_t* __restrict__ outFrag,
            int plain)
{
    int jt = blockIdx.x;
    int w = threadIdx.x >> 5, l = threadIdx.x & 31;
    int mt = w & 3, nh = w >> 2;

    float acc[3][4];
#pragma unroll
    for (int g = 0; g < 3; g++)
#pragma unroll
        for (int i = 0; i < 4; i++) acc[g][i] = 0.0f;

    const uint4* b0p = Bpk + ((size_t)(jt * 6 + 0 + nh) * K16N) * 32 + l;
    const uint4* b1p = Bpk + ((size_t)(jt * 6 + 2 + nh) * K16N) * 32 + l;
    const uint4* b2p = Bpk + ((size_t)(jt * 6 + 4 + nh) * K16N) * 32 + l;
    const uint32_t* ap = Af + ((size_t)mt * K16N * 32 + l) * 8;

    uint4 ah = *(const uint4*)ap;
    uint4 al = *(const uint4*)(ap + 4);
    uint4 b0 = *b0p, b1 = *b1p, b2 = *b2p;

    for (int k16 = 0; k16 < K16N; k16++) {
        uint4 ah2, al2, b0n, b1n, b2n;
        if (k16 + 1 < K16N) {
            ap += 256; b0p += 32; b1p += 32; b2p += 32;
            ah2 = *(const uint4*)ap;
            al2 = *(const uint4*)(ap + 4);
            b0n = *b0p; b1n = *b1p; b2n = *b2p;
        } else {
            ah2 = ah; al2 = al; b0n = b0; b1n = b1; b2n = b2;
        }
        // gate 0
        mma16816(acc[0], ah.x, ah.y, ah.z, ah.w, b0.x, b0.y);
        mma16816(acc[0], ah.x, ah.y, ah.z, ah.w, b0.z, b0.w);
        mma16816(acc[0], al.x, al.y, al.z, al.w, b0.x, b0.y);
        // gate 1
        mma16816(acc[1], ah.x, ah.y, ah.z, ah.w, b1.x, b1.y);
        mma16816(acc[1], ah.x, ah.y, ah.z, ah.w, b1.z, b1.w);
        mma16816(acc[1], al.x, al.y, al.z, al.w, b1.x, b1.y);
        // gate 2
        mma16816(acc[2], ah.x, ah.y, ah.z, ah.w, b2.x, b2.y);
        mma16816(acc[2], ah.x, ah.y, ah.z, ah.w, b2.z, b2.w);
        mma16816(acc[2], al.x, al.y, al.z, al.w, b2.x, b2.y);
        ah = ah2; al = al2; b0 = b0n; b1 = b1n; b2 = b2n;
    }

    // D mapping: acc[g][0]=(m0,c0) [1]=(m0,c1) [2]=(m1,c0) [3]=(m1,c1)
    int q = l >> 2, tp = l & 3;
    int m0 = mt * 16 + q, m1 = m0 + 8;
    int c0 = jt * 16 + nh * 8 + 2 * tp, c1 = c0 + 1;

    if (plain) {
#pragma unroll
        for (int g = 0; g < 3; g++) {
            float bb0 = bias[g * Hd + c0], bb1 = bias[g * Hd + c1];
            outH[(size_t)m0 * G3 + g * Hd + c0] = acc[g][0] + bb0;
            outH[(size_t)m0 * G3 + g * Hd + c1] = acc[g][1] + bb1;
            outH[(size_t)m1 * G3 + g * Hd + c0] = acc[g][2] + bb0;
            outH[(size_t)m1 * G3 + g * Hd + c1] = acc[g][3] + bb1;
        }
        return;
    }

    float br = bias[c0], brX = bias[c1];
    float bz = bias[Hd + c0], bzX = bias[Hd + c1];
    float bn = bias[2 * Hd + c0], bnX = bias[2 * Hd + c1];

    int ix0 = 0, ix1 = 0;
    if (Woh) { ix0 = idx[m0]; ix1 = idx[m1]; }

    float hout[4];
#pragma unroll
    for (int v = 0; v < 4; v++) {
        int b = (v & 2) ? m1 : m0;
        int c = (v & 1) ? c1 : c0;
        float gir = gi[(size_t)b * G3 + c];
        float giz = gi[(size_t)b * G3 + Hd + c];
        float gin = gi[(size_t)b * G3 + 2 * Hd + c];
        if (Woh) {
            int ix = (v & 2) ? ix1 : ix0;
            gir += Woh[(size_t)c * ldw_oh + ix];
            giz += Woh[(size_t)(Hd + c) * ldw_oh + ix];
            gin += Woh[(size_t)(2 * Hd + c) * ldw_oh + ix];
        }
        float ghr = acc[0][v] + ((v & 1) ? brX : br);
        float ghz = acc[1][v] + ((v & 1) ? bzX : bz);
        float ghn = acc[2][v] + ((v & 1) ? bnX : bn);
        float r = sigm_f(gir + ghr);
        float u = sigm_f(giz + ghz);
        float n = tanh_f(gin + r * ghn);
        float hp = Hfp[(size_t)b * Hd + c];
        hout[v] = (1.0f - u) * n + u * hp;
        outH[(size_t)b * Hd + c] = hout[v];
    }

    // fragment-layout write for next step's A operand
    uint32_t hi0, lo0, hi1, lo1;
    split2(hout[0], hout[1], hi0, lo0);   // row m0, cols c0,c1
    split2(hout[2], hout[3], hi1, lo1);   // row m1
    int lp = q * 4 + tp;
    uint32_t* fb = outFrag + (((size_t)mt * K16N + jt) * 32 + lp) * 8;
    fb[nh * 2 + 0] = hi0;
    fb[nh * 2 + 1] = hi1;
    fb[4 + nh * 2 + 0] = lo0;
    fb[4 + nh * 2 + 1] = lo1;
}

// ---------------- rhythm logits + log_softmax + argmax ---------------------------
__global__ void k_rhylog(const float* __restrict__ Hn, const float* __restrict__ wo0,
                         const float* __restrict__ bo0,
                         float* __restrict__ rlo, int* __restrict__ ridx)
{
    int b = blockIdx.x, tid = threadIdx.x;
    float p0 = 0.f, p1 = 0.f, p2 = 0.f;
    for (int k = tid; k < Hd; k += 128) {
        float h = Hn[(size_t)b * Hd + k];
        p0 += h * wo0[k];
        p1 += h * wo0[Hd + k];
        p2 += h * wo0[2 * Hd + k];
    }
    __shared__ float s0[128], s1[128], s2[128];
    s0[tid] = p0; s1[tid] = p1; s2[tid] = p2;
    __syncthreads();
    for (int off = 64; off > 0; off >>= 1) {
        if (tid < off) {
            s0[tid] += s0[tid + off];
            s1[tid] += s1[tid + off];
            s2[tid] += s2[tid + off];
        }
        __syncthreads();
    }
    if (tid == 0) {
        float l0 = s0[0] + bo0[0], l1 = s1[0] + bo0[1], l2 = s2[0] + bo0[2];
        float m = fmaxf(l0, fmaxf(l1, l2));
        float z = m + logf(expf(l0 - m) + expf(l1 - m) + expf(l2 - m));
        rlo[b * 3 + 0] = l0 - z;
        rlo[b * 3 + 1] = l1 - z;
        rlo[b * 3 + 2] = l2 - z;
        int ix = 0; float bv = l0;
        if (l1 > bv) { bv = l1; ix = 1; }
        if (l2 > bv) { bv = l2; ix = 2; }
        ridx[b] = ix;
    }
}

// ---------------- build gi1t[t][b][:] -------------------------------------------
__global__ void k_gi1t(const float* __restrict__ gi1z,
                       const float* __restrict__ cond,
                       const float* __restrict__ rlo,
                       const float* __restrict__ w_ih1,
                       float* __restrict__ gi1t)
{
    int n = blockIdx.x * 256 + threadIdx.x;
    int t = blockIdx.y;
    float wr[RHYN], wc[CHN];
#pragma unroll
    for (int j = 0; j < RHYN; j++) wr[j] = w_ih1[(size_t)n * 273 + MELN + j];
#pragma unroll
    for (int j = 0; j < CHN; j++) wc[j] = w_ih1[(size_t)n * 273 + MELN + RHYN + 128 + j];
    for (int b = 0; b < NB; b++) {
        float s = gi1z[(size_t)b * G3 + n];
        const float* r = &rlo[(t * NB + b) * RHYN];
        s += r[0] * wr[0] + r[1] * wr[1] + r[2] * wr[2];
        const float* c = &cond[(b * TT + t) * CHN];
#pragma unroll
        for (int j = 0; j < CHN; j++) s += c[j] * wc[j];
        gi1t[((size_t)t * NB + b) * G3 + n] = s;
    }
}

// ---------------- melody logits + log_softmax + argmax + output ------------------
__global__ void k_mellog(const float* __restrict__ Hn, const float* __restrict__ wo1,
                         const float* __restrict__ bo1,
                         float* __restrict__ outmel, int t, int* __restrict__ midx)
{
    __shared__ __align__(16) float hs[Hd];
    __shared__ float ls[MELN];
    __shared__ float red[256];
    int b = blockIdx.x, tid = threadIdx.x;
    for (int k = tid; k < Hd; k += 256) hs[k] = Hn[(size_t)b * Hd + k];
    __syncthreads();
    if (tid < MELN) {
        const float4* w4 = (const float4*)(wo1 + (size_t)tid * Hd);
        const float4* h4 = (const float4*)hs;
        float s = 0.f;
#pragma unroll 4
        for (int k = 0; k < Hd / 4; k++) {
            float4 a = h4[k], w = w4[k];
            s += a.x * w.x + a.y * w.y + a.z * w.z + a.w * w.w;
        }
        ls[tid] = s + bo1[tid];
    }
    __syncthreads();
    red[tid] = (tid < MELN) ? ls[tid] : -3.4e38f;
    __syncthreads();
    for (int off = 128; off > 0; off >>= 1) {
        if (tid < off) red[tid] = fmaxf(red[tid], red[tid + off]);
        __syncthreads();
    }
    float m = red[0];
    __syncthreads();
    red[tid] = (tid < MELN) ? expf(ls[tid] - m) : 0.f;
    __syncthreads();
    for (int off = 128; off > 0; off >>= 1) {
        if (tid < off) red[tid] += red[tid + off];
        __syncthreads();
    }
    float z = m + logf(red[0]);
    if (tid < MELN)
        outmel[((size_t)b * TT + t) * MELN + tid] = ls[tid] - z;
    if (tid == 0) {
        int ix = 0; float bv = ls[0];
        for (int c = 1; c < MELN; c++) if (ls[c] > bv) { bv = ls[c]; ix = c; }
        midx[b] = ix;
    }
}

// ---------------- host driver ----------------------------------------------------
extern "C" void kernel_launch(void* const* d_in, const int* in_sizes, int n_in,
                              void* d_out, int out_size)
{
    const float* z1    = (const float*)d_in[0];
    const float* z2    = (const float*)d_in[1];
    const float* cond  = (const float*)d_in[2];
    const float* w_ih0 = (const float*)d_in[3];
    const float* w_hh0 = (const float*)d_in[4];
    const float* b_ih0 = (const float*)d_in[5];
    const float* b_hh0 = (const float*)d_in[6];
    const float* w_ih1 = (const float*)d_in[7];
    const float* w_hh1 = (const float*)d_in[8];
    const float* b_ih1 = (const float*)d_in[9];
    const float* b_hh1 = (const float*)d_in[10];
    const float* w_ih2 = (const float*)d_in[11];
    const float* w_hh2 = (const float*)d_in[12];
    const float* b_ih2 = (const float*)d_in[13];
    const float* b_hh2 = (const float*)d_in[14];
    const float* wi0   = (const float*)d_in[15];
    const float* bi0   = (const float*)d_in[16];
    const float* wo0   = (const float*)d_in[17];
    const float* bo0   = (const float*)d_in[18];
    const float* wi1   = (const float*)d_in[19];
    const float* bi1   = (const float*)d_in[20];
    const float* wo1   = (const float*)d_in[21];
    const float* bo1   = (const float*)d_in[22];
    float* out = (float*)d_out;

    float *hB, *haB, *hbB, *gic0, *gi1z, *gi1t, *gi2, *rlo;
    int *ridx, *midx;
    uint4 *Bp0, *Bp1, *Bp2i, *Bp2h;
    uint32_t *hfr, *hafr, *hbfr;
    cudaGetSymbolAddress((void**)&hB,   g_h);
    cudaGetSymbolAddress((void**)&haB,  g_ha);
    cudaGetSymbolAddress((void**)&hbB,  g_hb);
    cudaGetSymbolAddress((void**)&gic0, g_gic0);
    cudaGetSymbolAddress((void**)&gi1z, g_gi1z);
    cudaGetSymbolAddress((void**)&gi1t, g_gi1t);
    cudaGetSymbolAddress((void**)&gi2,  g_gi2);
    cudaGetSymbolAddress((void**)&rlo,  g_rlo);
    cudaGetSymbolAddress((void**)&ridx, g_ridx);
    cudaGetSymbolAddress((void**)&midx, g_midx);
    cudaGetSymbolAddress((void**)&Bp0,  g_Bp0);
    cudaGetSymbolAddress((void**)&Bp1,  g_Bp1);
    cudaGetSymbolAddress((void**)&Bp2i, g_Bp2i);
    cudaGetSymbolAddress((void**)&Bp2h, g_Bp2h);
    cudaGetSymbolAddress((void**)&hfr,  g_hfrag);
    cudaGetSymbolAddress((void**)&hafr, g_hafrag);
    cudaGetSymbolAddress((void**)&hbfr, g_hbfrag);

    float* hbuf[2]  = { hB,  hB  + NB * Hd };
    float* habuf[2] = { haB, haB + NB * Hd };
    float* hbbuf[2] = { hbB, hbB + NB * Hd };
    uint32_t* hfrag[2]  = { hfr,  hfr  + FRAGU32 };
    uint32_t* hafrag[2] = { hafr, hafr + FRAGU32 };
    uint32_t* hbfrag[2] = { hbfr, hbfr + FRAGU32 };

    k_init_idx<<<1, 64>>>(ridx, midx);

    // pack weights into mma fragment layout (hi/lo split)
    k_pack<<<BPKSZ / 256, 256>>>(w_hh0, Bp0);
    k_pack<<<BPKSZ / 256, 256>>>(w_hh1, Bp1);
    k_pack<<<BPKSZ / 256, 256>>>(w_ih2, Bp2i);
    k_pack<<<BPKSZ / 256, 256>>>(w_hh2, Bp2h);

    // initial hiddens + constant gi parts
    k_mv<<<dim3(Hd / 256, NB), 256>>>(z2, 128, wi0, 128, 0, bi0, Hd, hbuf[0], 1);
    k_mv<<<dim3(Hd / 256, NB), 256>>>(z1, 128, wi1, 128, 0, bi1, Hd, habuf[0], 1);
    k_mv<<<dim3(G3 / 256, NB), 256>>>(z2, 128, w_ih0, 131, RHYN, b_ih0, G3, gic0, 0);
    k_mv<<<dim3(G3 / 256, NB), 256>>>(z1, 128, w_ih1, 273, MELN + RHYN, b_ih1, G3, gi1z, 0);
    k_h2frag<<<64, 256>>>(hbuf[0], hfrag[0]);
    k_h2frag<<<64, 256>>>(habuf[0], hafrag[0]);

    // ---- rhythm phase ----
    for (int t = 0; t < TT; t++) {
        k_gemm<<<128, 256>>>(Bp0, hfrag[t & 1], hbuf[t & 1], b_hh0, gic0,
                             w_ih0, 131, ridx + t * NB,
                             hbuf[(t + 1) & 1], hfrag[(t + 1) & 1], 0);
        k_rhylog<<<NB, 128>>>(hbuf[(t + 1) & 1], wo0, bo0,
                              rlo + t * NB * RHYN, ridx + (t + 1) * NB);
    }

    // ---- per-step gi for melody GRU1 ----
    k_gi1t<<<dim3(G3 / 256, TT), 256>>>(gi1z, cond, rlo, w_ih1, gi1t);

    // ---- melody phase ----
    for (int t = 0; t < TT; t++) {
        // GRU1: ha' from ha
        k_gemm<<<128, 256>>>(Bp1, hafrag[t & 1], habuf[t & 1], b_hh1,
                             gi1t + (size_t)t * NB * G3,
                             w_ih1, 273, midx + t * NB,
                             habuf[(t + 1) & 1], hafrag[(t + 1) & 1], 0);
        // gi2 = ha' @ w_ih2^T + b_ih2
        k_gemm<<<128, 256>>>(Bp2i, hafrag[(t + 1) & 1], nullptr, b_ih2,
                             nullptr, nullptr, 0, nullptr,
                             gi2, nullptr, 1);
        // GRU2: hb' from hb (t=0: from ha')
        const uint32_t* fIn = (t == 0) ? hafrag[1] : hbfrag[t & 1];
        const float* fpIn   = (t == 0) ? habuf[1]  : hbbuf[t & 1];
        k_gemm<<<128, 256>>>(Bp2h, fIn, fpIn, b_hh2, gi2,
                             nullptr, 0, nullptr,
                             hbbuf[(t + 1) & 1], hbfrag[(t + 1) & 1], 0);
        k_mellog<<<NB, 256>>>(hbbuf[(t + 1) & 1], wo1, bo1, out, t, midx + (t + 1) * NB);
    }
}

// round 5
// speedup vs baseline: 3.1747x; 1.3971x over previous
#include <cuda_runtime.h>
#include <cuda_bf16.h>
#include <math.h>
#include <stdint.h>
#include <stddef.h>

#define NB   64
#define Hd   2048
#define G3   6144
#define TT   32
#define MELN 130
#define CHN  12
#define RHYN 3
#define NTILE 768          // G3/8
#define K16N  128          // Hd/16
#define FRAGU32 (4*K16N*32*8)   // 131072 u32 per H operand
#define BPKSZ (NTILE*K16N*32)   // uint4 count per packed weight matrix

// ---------------- device scratch ------------------------------------------------
__device__ float g_h[2 * NB * Hd];
__device__ float g_ha[2 * NB * Hd];
__device__ float g_hb[2 * NB * Hd];
__device__ float g_gic0[NB * G3];
__device__ float g_gi1z[NB * G3];
__device__ float g_gi1t[(size_t)TT * NB * G3];
__device__ float g_gi2[NB * G3];
__device__ float g_rlo[TT * NB * RHYN];
__device__ int   g_ridx[(TT + 1) * NB];
__device__ int   g_midx[(TT + 1) * NB];

__device__ uint4 g_Bp0[BPKSZ];    // packed w_hh0 (hi/lo)
__device__ uint4 g_Bp1[BPKSZ];    // packed w_hh1
__device__ uint4 g_Bp2i[BPKSZ];   // packed w_ih2
__device__ uint4 g_Bp2h[BPKSZ];   // packed w_hh2

__device__ uint32_t g_hfrag[2][FRAGU32];
__device__ uint32_t g_hafrag[2][FRAGU32];
__device__ uint32_t g_hbfrag[2][FRAGU32];

// accurate-even-under-fast-math activations
__device__ __forceinline__ float sigm_f(float x) { return 1.0f / (1.0f + expf(-x)); }
__device__ __forceinline__ float tanh_f(float x) { return 1.0f - 2.0f / (expf(2.0f * x) + 1.0f); }

__device__ __forceinline__ uint32_t packbf2(float x, float y) {
    __nv_bfloat162 v = __floats2bfloat162_rn(x, y);
    return *reinterpret_cast<uint32_t*>(&v);
}
__device__ __forceinline__ void split2(float x, float y, uint32_t& hi, uint32_t& lo) {
    __nv_bfloat16 hx = __float2bfloat16(x), hy = __float2bfloat16(y);
    float rx = x - __bfloat162float(hx);
    float ry = y - __bfloat162float(hy);
    __nv_bfloat162 H; H.x = hx; H.y = hy;
    hi = *reinterpret_cast<uint32_t*>(&H);
    lo = packbf2(rx, ry);
}

__device__ __forceinline__ void mma16816(float* d,
                                         uint32_t a0, uint32_t a1, uint32_t a2, uint32_t a3,
                                         uint32_t b0, uint32_t b1) {
    asm volatile(
        "mma.sync.aligned.m16n8k16.row.col.f32.bf16.bf16.f32 "
        "{%0,%1,%2,%3}, {%4,%5,%6,%7}, {%8,%9}, {%0,%1,%2,%3};"
        : "+f"(d[0]), "+f"(d[1]), "+f"(d[2]), "+f"(d[3])
        : "r"(a0), "r"(a1), "r"(a2), "r"(a3), "r"(b0), "r"(b1));
}

// one k16 step: 9 MMAs, gates round-robin so each acc is revisited every 3rd MMA
__device__ __forceinline__ void mma_step(float acc[3][4], const uint4& ah, const uint4& al,
                                         const uint4& b0, const uint4& b1, const uint4& b2) {
    mma16816(acc[0], ah.x, ah.y, ah.z, ah.w, b0.x, b0.y);
    mma16816(acc[1], ah.x, ah.y, ah.z, ah.w, b1.x, b1.y);
    mma16816(acc[2], ah.x, ah.y, ah.z, ah.w, b2.x, b2.y);
    mma16816(acc[0], ah.x, ah.y, ah.z, ah.w, b0.z, b0.w);
    mma16816(acc[1], ah.x, ah.y, ah.z, ah.w, b1.z, b1.w);
    mma16816(acc[2], ah.x, ah.y, ah.z, ah.w, b2.z, b2.w);
    mma16816(acc[0], al.x, al.y, al.z, al.w, b0.x, b0.y);
    mma16816(acc[1], al.x, al.y, al.z, al.w, b1.x, b1.y);
    mma16816(acc[2], al.x, al.y, al.z, al.w, b2.x, b2.y);
}

// ---------------- misc small kernels --------------------------------------------
__global__ void k_init_idx(int* ridx, int* midx) {
    int i = threadIdx.x;
    if (i < NB) { ridx[i] = RHYN - 1; midx[i] = MELN - 1; }
}

__global__ void k_mv(const float* __restrict__ x, int K,
                     const float* __restrict__ W, int ldw, int off,
                     const float* __restrict__ bias, int N,
                     float* __restrict__ out, int act)
{
    __shared__ float xs[128];
    int b = blockIdx.y;
    if (threadIdx.x < K) xs[threadIdx.x] = x[b * K + threadIdx.x];
    __syncthreads();
    int n = blockIdx.x * 256 + threadIdx.x;
    if (n >= N) return;
    float acc = bias[n];
    const float* wr = W + (size_t)n * ldw + off;
#pragma unroll 8
    for (int k = 0; k < K; k++) acc += xs[k] * wr[k];
    if (act) acc = tanh_f(acc);
    out[b * N + n] = acc;
}

// ---------------- weight packer: W[6144,2048] fp32 -> fragment-linear hi/lo ------
__global__ void k_pack(const float* __restrict__ W, uint4* __restrict__ out)
{
    int id = blockIdx.x * 256 + threadIdx.x;
    int l = id & 31;
    int nt = id >> 12;
    int P = nt * 8 + (l >> 2);
    int jt = P / 48, rem = P % 48;
    int g = rem >> 4, c = rem & 15;
    int k16 = (id >> 5) & 127;
    const float* wr = W + (size_t)(g * Hd + jt * 16 + c) * Hd + k16 * 16 + 2 * (l & 3);
    float x0 = wr[0], x1 = wr[1], x8 = wr[8], x9 = wr[9];
    uint32_t h01, l01, h89, l89;
    split2(x0, x1, h01, l01);
    split2(x8, x9, h89, l89);
    out[id] = make_uint4(h01, h89, l01, l89);
}

// ---------------- H fp32 -> fragment-layout hi/lo --------------------------------
__global__ void k_h2frag(const float* __restrict__ H, uint32_t* __restrict__ Af)
{
    int id = blockIdx.x * 256 + threadIdx.x;
    int l = id & 31;
    int k16 = (id >> 5) & 127;
    int mt = id >> 12;
    int m0 = mt * 16 + (l >> 2);
    int k0 = k16 * 16 + 2 * (l & 3);
    const float* r0 = H + (size_t)m0 * Hd + k0;
    const float* r1 = H + (size_t)(m0 + 8) * Hd + k0;
    uint32_t* o = Af + (size_t)id * 8;
    uint32_t hi, lo;
    split2(r0[0], r0[1], hi, lo); o[0] = hi; o[4] = lo;
    split2(r1[0], r1[1], hi, lo); o[1] = hi; o[5] = lo;
    split2(r0[8], r0[9], hi, lo); o[2] = hi; o[6] = lo;
    split2(r1[8], r1[9], hi, lo); o[3] = hi; o[7] = lo;
}

// ---------------- tensor-core GEMM + fused GRU epilogue --------------------------
// grid = 128 (jt), block = 512 (16 warps = 4 m-tiles x 2 n-halves x 2 k-halves).
__global__ __launch_bounds__(512, 1)
void k_gemm(const uint4* __restrict__ Bpk,
            const uint32_t* __restrict__ Af,
            const float* __restrict__ Hfp,
            const float* __restrict__ bias,
            const float* __restrict__ gi,
            const float* __restrict__ Woh, int ldw_oh,
            const int* __restrict__ idx,
            float* __restrict__ outH,
            uint32_t* __restrict__ outFrag,
            int plain)
{
    __shared__ float sred[8][32][12];
    int jt = blockIdx.x;
    int w = threadIdx.x >> 5, l = threadIdx.x & 31;
    int mt = w & 3;          // m tile
    int nh = (w >> 2) & 1;   // n half
    int kh = w >> 3;         // k half
    const int KH = K16N / 2; // 64

    float acc[3][4];
#pragma unroll
    for (int g = 0; g < 3; g++)
#pragma unroll
        for (int i = 0; i < 4; i++) acc[g][i] = 0.0f;

    const uint4* b0p = Bpk + ((size_t)(jt * 6 + 0 + nh) * K16N + kh * KH) * 32 + l;
    const uint4* b1p = Bpk + ((size_t)(jt * 6 + 2 + nh) * K16N + kh * KH) * 32 + l;
    const uint4* b2p = Bpk + ((size_t)(jt * 6 + 4 + nh) * K16N + kh * KH) * 32 + l;
    const uint32_t* ap = Af + (((size_t)mt * K16N + kh * KH) * 32 + l) * 8;

    uint4 ah = *(const uint4*)ap;
    uint4 al = *(const uint4*)(ap + 4);
    uint4 b0 = *b0p, b1 = *b1p, b2 = *b2p;

#pragma unroll 4
    for (int k16 = 0; k16 < KH - 1; k16++) {
        ap += 256; b0p += 32; b1p += 32; b2p += 32;
        uint4 ah2 = *(const uint4*)ap;
        uint4 al2 = *(const uint4*)(ap + 4);
        uint4 b0n = *b0p, b1n = *b1p, b2n = *b2p;
        mma_step(acc, ah, al, b0, b1, b2);
        ah = ah2; al = al2; b0 = b0n; b1 = b1n; b2 = b2n;
    }
    mma_step(acc, ah, al, b0, b1, b2);

    // combine k-halves: warps 8..15 dump, warps 0..7 add + epilogue
    if (kh == 1) {
#pragma unroll
        for (int g = 0; g < 3; g++)
#pragma unroll
            for (int i = 0; i < 4; i++) sred[w & 7][l][g * 4 + i] = acc[g][i];
    }
    __syncthreads();
    if (kh == 1) return;
#pragma unroll
    for (int g = 0; g < 3; g++)
#pragma unroll
        for (int i = 0; i < 4; i++) acc[g][i] += sred[w][l][g * 4 + i];

    // D mapping: acc[g][0]=(m0,c0) [1]=(m0,c1) [2]=(m1,c0) [3]=(m1,c1)
    int q = l >> 2, tp = l & 3;
    int m0 = mt * 16 + q, m1 = m0 + 8;
    int c0 = jt * 16 + nh * 8 + 2 * tp, c1 = c0 + 1;

    if (plain) {
#pragma unroll
        for (int g = 0; g < 3; g++) {
            float bb0 = bias[g * Hd + c0], bb1 = bias[g * Hd + c1];
            outH[(size_t)m0 * G3 + g * Hd + c0] = acc[g][0] + bb0;
            outH[(size_t)m0 * G3 + g * Hd + c1] = acc[g][1] + bb1;
            outH[(size_t)m1 * G3 + g * Hd + c0] = acc[g][2] + bb0;
            outH[(size_t)m1 * G3 + g * Hd + c1] = acc[g][3] + bb1;
        }
        return;
    }

    float br = bias[c0], brX = bias[c1];
    float bz = bias[Hd + c0], bzX = bias[Hd + c1];
    float bn = bias[2 * Hd + c0], bnX = bias[2 * Hd + c1];

    int ix0 = 0, ix1 = 0;
    if (Woh) { ix0 = idx[m0]; ix1 = idx[m1]; }

    float hout[4];
#pragma unroll
    for (int v = 0; v < 4; v++) {
        int b = (v & 2) ? m1 : m0;
        int c = (v & 1) ? c1 : c0;
        float gir = gi[(size_t)b * G3 + c];
        float giz = gi[(size_t)b * G3 + Hd + c];
        float gin = gi[(size_t)b * G3 + 2 * Hd + c];
        if (Woh) {
            int ix = (v & 2) ? ix1 : ix0;
            gir += Woh[(size_t)c * ldw_oh + ix];
            giz += Woh[(size_t)(Hd + c) * ldw_oh + ix];
            gin += Woh[(size_t)(2 * Hd + c) * ldw_oh + ix];
        }
        float ghr = acc[0][v] + ((v & 1) ? brX : br);
        float ghz = acc[1][v] + ((v & 1) ? bzX : bz);
        float ghn = acc[2][v] + ((v & 1) ? bnX : bn);
        float r = sigm_f(gir + ghr);
        float u = sigm_f(giz + ghz);
        float n = tanh_f(gin + r * ghn);
        float hp = Hfp[(size_t)b * Hd + c];
        hout[v] = (1.0f - u) * n + u * hp;
        outH[(size_t)b * Hd + c] = hout[v];
    }

    uint32_t hi0, lo0, hi1, lo1;
    split2(hout[0], hout[1], hi0, lo0);
    split2(hout[2], hout[3], hi1, lo1);
    int lp = q * 4 + tp;
    uint32_t* fb = outFrag + (((size_t)mt * K16N + jt) * 32 + lp) * 8;
    fb[nh * 2 + 0] = hi0;
    fb[nh * 2 + 1] = hi1;
    fb[4 + nh * 2 + 0] = lo0;
    fb[4 + nh * 2 + 1] = lo1;
}

// ---------------- rhythm logits + log_softmax + argmax ---------------------------
__global__ void k_rhylog(const float* __restrict__ Hn, const float* __restrict__ wo0,
                         const float* __restrict__ bo0,
                         float* __restrict__ rlo, int* __restrict__ ridx)
{
    int b = blockIdx.x, tid = threadIdx.x;
    float p0 = 0.f, p1 = 0.f, p2 = 0.f;
    for (int k = tid; k < Hd; k += 128) {
        float h = Hn[(size_t)b * Hd + k];
        p0 += h * wo0[k];
        p1 += h * wo0[Hd + k];
        p2 += h * wo0[2 * Hd + k];
    }
    __shared__ float s0[128], s1[128], s2[128];
    s0[tid] = p0; s1[tid] = p1; s2[tid] = p2;
    __syncthreads();
    for (int off = 64; off > 0; off >>= 1) {
        if (tid < off) {
            s0[tid] += s0[tid + off];
            s1[tid] += s1[tid + off];
            s2[tid] += s2[tid + off];
        }
        __syncthreads();
    }
    if (tid == 0) {
        float l0 = s0[0] + bo0[0], l1 = s1[0] + bo0[1], l2 = s2[0] + bo0[2];
        float m = fmaxf(l0, fmaxf(l1, l2));
        float z = m + logf(expf(l0 - m) + expf(l1 - m) + expf(l2 - m));
        rlo[b * 3 + 0] = l0 - z;
        rlo[b * 3 + 1] = l1 - z;
        rlo[b * 3 + 2] = l2 - z;
        int ix = 0; float bv = l0;
        if (l1 > bv) { bv = l1; ix = 1; }
        if (l2 > bv) { bv = l2; ix = 2; }
        ridx[b] = ix;
    }
}

// ---------------- build gi1t[t][b][:] -------------------------------------------
__global__ void k_gi1t(const float* __restrict__ gi1z,
                       const float* __restrict__ cond,
                       const float* __restrict__ rlo,
                       const float* __restrict__ w_ih1,
                       float* __restrict__ gi1t)
{
    int n = blockIdx.x * 256 + threadIdx.x;
    int t = blockIdx.y;
    float wr[RHYN], wc[CHN];
#pragma unroll
    for (int j = 0; j < RHYN; j++) wr[j] = w_ih1[(size_t)n * 273 + MELN + j];
#pragma unroll
    for (int j = 0; j < CHN; j++) wc[j] = w_ih1[(size_t)n * 273 + MELN + RHYN + 128 + j];
    for (int b = 0; b < NB; b++) {
        float s = gi1z[(size_t)b * G3 + n];
        const float* r = &rlo[(t * NB + b) * RHYN];
        s += r[0] * wr[0] + r[1] * wr[1] + r[2] * wr[2];
        const float* c = &cond[(b * TT + t) * CHN];
#pragma unroll
        for (int j = 0; j < CHN; j++) s += c[j] * wc[j];
        gi1t[((size_t)t * NB + b) * G3 + n] = s;
    }
}

// ---------------- melody logits + log_softmax + argmax + output ------------------
// grid 64 (b), block 256: warp-per-row dots with shuffle reduction
__global__ void k_mellog(const float* __restrict__ Hn, const float* __restrict__ wo1,
                         const float* __restrict__ bo1,
                         float* __restrict__ outmel, int t, int* __restrict__ midx)
{
    __shared__ __align__(16) float hs[Hd];
    __shared__ float ls[MELN];
    __shared__ float red[256];
    int b = blockIdx.x, tid = threadIdx.x;
    int w = tid >> 5, l = tid & 31;
    for (int k = tid; k < Hd; k += 256) hs[k] = Hn[(size_t)b * Hd + k];
    __syncthreads();
    const float4* h4 = (const float4*)hs;
    for (int r = w; r < MELN; r += 8) {
        const float4* w4 = (const float4*)(wo1 + (size_t)r * Hd);
        float s = 0.f;
#pragma unroll
        for (int c = l; c < Hd / 4; c += 32) {
            float4 a = h4[c], q = w4[c];
            s += a.x * q.x + a.y * q.y + a.z * q.z + a.w * q.w;
        }
#pragma unroll
        for (int off = 16; off > 0; off >>= 1) s += __shfl_xor_sync(0xffffffffu, s, off);
        if (l == 0) ls[r] = s + bo1[r];
    }
    __syncthreads();
    red[tid] = (tid < MELN) ? ls[tid] : -3.4e38f;
    __syncthreads();
    for (int off = 128; off > 0; off >>= 1) {
        if (tid < off) red[tid] = fmaxf(red[tid], red[tid + off]);
        __syncthreads();
    }
    float m = red[0];
    __syncthreads();
    red[tid] = (tid < MELN) ? expf(ls[tid] - m) : 0.f;
    __syncthreads();
    for (int off = 128; off > 0; off >>= 1) {
        if (tid < off) red[tid] += red[tid + off];
        __syncthreads();
    }
    float z = m + logf(red[0]);
    if (tid < MELN)
        outmel[((size_t)b * TT + t) * MELN + tid] = ls[tid] - z;
    if (tid == 0) {
        int ix = 0; float bv = ls[0];
        for (int c = 1; c < MELN; c++) if (ls[c] > bv) { bv = ls[c]; ix = c; }
        midx[b] = ix;
    }
}

// ---------------- host driver ----------------------------------------------------
extern "C" void kernel_launch(void* const* d_in, const int* in_sizes, int n_in,
                              void* d_out, int out_size)
{
    const float* z1    = (const float*)d_in[0];
    const float* z2    = (const float*)d_in[1];
    const float* cond  = (const float*)d_in[2];
    const float* w_ih0 = (const float*)d_in[3];
    const float* w_hh0 = (const float*)d_in[4];
    const float* b_ih0 = (const float*)d_in[5];
    const float* b_hh0 = (const float*)d_in[6];
    const float* w_ih1 = (const float*)d_in[7];
    const float* w_hh1 = (const float*)d_in[8];
    const float* b_ih1 = (const float*)d_in[9];
    const float* b_hh1 = (const float*)d_in[10];
    const float* w_ih2 = (const float*)d_in[11];
    const float* w_hh2 = (const float*)d_in[12];
    const float* b_ih2 = (const float*)d_in[13];
    const float* b_hh2 = (const float*)d_in[14];
    const float* wi0   = (const float*)d_in[15];
    const float* bi0   = (const float*)d_in[16];
    const float* wo0   = (const float*)d_in[17];
    const float* bo0   = (const float*)d_in[18];
    const float* wi1   = (const float*)d_in[19];
    const float* bi1   = (const float*)d_in[20];
    const float* wo1   = (const float*)d_in[21];
    const float* bo1   = (const float*)d_in[22];
    float* out = (float*)d_out;

    float *hB, *haB, *hbB, *gic0, *gi1z, *gi1t, *gi2, *rlo;
    int *ridx, *midx;
    uint4 *Bp0, *Bp1, *Bp2i, *Bp2h;
    uint32_t *hfr, *hafr, *hbfr;
    cudaGetSymbolAddress((void**)&hB,   g_h);
    cudaGetSymbolAddress((void**)&haB,  g_ha);
    cudaGetSymbolAddress((void**)&hbB,  g_hb);
    cudaGetSymbolAddress((void**)&gic0, g_gic0);
    cudaGetSymbolAddress((void**)&gi1z, g_gi1z);
    cudaGetSymbolAddress((void**)&gi1t, g_gi1t);
    cudaGetSymbolAddress((void**)&gi2,  g_gi2);
    cudaGetSymbolAddress((void**)&rlo,  g_rlo);
    cudaGetSymbolAddress((void**)&ridx, g_ridx);
    cudaGetSymbolAddress((void**)&midx, g_midx);
    cudaGetSymbolAddress((void**)&Bp0,  g_Bp0);
    cudaGetSymbolAddress((void**)&Bp1,  g_Bp1);
    cudaGetSymbolAddress((void**)&Bp2i, g_Bp2i);
    cudaGetSymbolAddress((void**)&Bp2h, g_Bp2h);
    cudaGetSymbolAddress((void**)&hfr,  g_hfrag);
    cudaGetSymbolAddress((void**)&hafr, g_hafrag);
    cudaGetSymbolAddress((void**)&hbfr, g_hbfrag);

    float* hbuf[2]  = { hB,  hB  + NB * Hd };
    float* habuf[2] = { haB, haB + NB * Hd };
    float* hbbuf[2] = { hbB, hbB + NB * Hd };
    uint32_t* hfrag[2]  = { hfr,  hfr  + FRAGU32 };
    uint32_t* hafrag[2] = { hafr, hafr + FRAGU32 };
    uint32_t* hbfrag[2] = { hbfr, hbfr + FRAGU32 };

    k_init_idx<<<1, 64>>>(ridx, midx);

    k_pack<<<BPKSZ / 256, 256>>>(w_hh0, Bp0);
    k_pack<<<BPKSZ / 256, 256>>>(w_hh1, Bp1);
    k_pack<<<BPKSZ / 256, 256>>>(w_ih2, Bp2i);
    k_pack<<<BPKSZ / 256, 256>>>(w_hh2, Bp2h);

    k_mv<<<dim3(Hd / 256, NB), 256>>>(z2, 128, wi0, 128, 0, bi0, Hd, hbuf[0], 1);
    k_mv<<<dim3(Hd / 256, NB), 256>>>(z1, 128, wi1, 128, 0, bi1, Hd, habuf[0], 1);
    k_mv<<<dim3(G3 / 256, NB), 256>>>(z2, 128, w_ih0, 131, RHYN, b_ih0, G3, gic0, 0);
    k_mv<<<dim3(G3 / 256, NB), 256>>>(z1, 128, w_ih1, 273, MELN + RHYN, b_ih1, G3, gi1z, 0);
    k_h2frag<<<64, 256>>>(hbuf[0], hfrag[0]);
    k_h2frag<<<64, 256>>>(habuf[0], hafrag[0]);

    // ---- rhythm phase ----
    for (int t = 0; t < TT; t++) {
        k_gemm<<<128, 512>>>(Bp0, hfrag[t & 1], hbuf[t & 1], b_hh0, gic0,
                             w_ih0, 131, ridx + t * NB,
                             hbuf[(t + 1) & 1], hfrag[(t + 1) & 1], 0);
        k_rhylog<<<NB, 128>>>(hbuf[(t + 1) & 1], wo0, bo0,
                              rlo + t * NB * RHYN, ridx + (t + 1) * NB);
    }

    // ---- per-step gi for melody GRU1 ----
    k_gi1t<<<dim3(G3 / 256, TT), 256>>>(gi1z, cond, rlo, w_ih1, gi1t);

    // ---- melody phase ----
    for (int t = 0; t < TT; t++) {
        k_gemm<<<128, 512>>>(Bp1, hafrag[t & 1], habuf[t & 1], b_hh1,
                             gi1t + (size_t)t * NB * G3,
                             w_ih1, 273, midx + t * NB,
                             habuf[(t + 1) & 1], hafrag[(t + 1) & 1], 0);
        k_gemm<<<128, 512>>>(Bp2i, hafrag[(t + 1) & 1], nullptr, b_ih2,
                             nullptr, nullptr, 0, nullptr,
                             gi2, nullptr, 1);
        const uint32_t* fIn = (t == 0) ? hafrag[1] : hbfrag[t & 1];
        const float* fpIn   = (t == 0) ? habuf[1]  : hbbuf[t & 1];
        k_gemm<<<128, 512>>>(Bp2h, fIn, fpIn, b_hh2, gi2,
                             nullptr, 0, nullptr,
                             hbbuf[(t + 1) & 1], hbfrag[(t + 1) & 1], 0);
        k_mellog<<<NB, 256>>>(hbbuf[(t + 1) & 1], wo1, bo1, out, t, midx + (t + 1) * NB);
    }
}

// round 6
// speedup vs baseline: 3.1826x; 1.0025x over previous
#include <cuda_runtime.h>
#include <cuda_bf16.h>
#include <math.h>
#include <stdint.h>
#include <stddef.h>

#define NB   64
#define Hd   2048
#define G3   6144
#define TT   32
#define MELN 130
#define CHN  12
#define RHYN 3
#define NTILE 768          // G3/8
#define K16N  128          // Hd/16
#define FRAGU32 (4*K16N*32*8)   // 131072 u32 per H operand
#define BPKSZ (NTILE*K16N*32)   // uint4 count per packed weight matrix

// ---------------- device scratch ------------------------------------------------
__device__ float g_h[2 * NB * Hd];
__device__ float g_ha[2 * NB * Hd];
__device__ float g_hb[2 * NB * Hd];
__device__ float g_gic0[NB * G3];
__device__ float g_gi1z[NB * G3];
__device__ float g_gi1t[(size_t)TT * NB * G3];
__device__ float g_gi2[NB * G3];
__device__ float g_rlo[TT * NB * RHYN];
__device__ int   g_ridx[(TT + 1) * NB];
__device__ int   g_midx[(TT + 1) * NB];

__device__ uint4 g_Bp0[BPKSZ];    // packed w_hh0 (hi/lo)
__device__ uint4 g_Bp1[BPKSZ];    // packed w_hh1
__device__ uint4 g_Bp2i[BPKSZ];   // packed w_ih2
__device__ uint4 g_Bp2h[BPKSZ];   // packed w_hh2

__device__ uint32_t g_hfrag[2][FRAGU32];
__device__ uint32_t g_hafrag[2][FRAGU32];
__device__ uint32_t g_hbfrag[2][FRAGU32];

// accurate-even-under-fast-math activations
__device__ __forceinline__ float sigm_f(float x) { return 1.0f / (1.0f + expf(-x)); }
__device__ __forceinline__ float tanh_f(float x) { return 1.0f - 2.0f / (expf(2.0f * x) + 1.0f); }

__device__ __forceinline__ uint32_t packbf2(float x, float y) {
    __nv_bfloat162 v = __floats2bfloat162_rn(x, y);
    return *reinterpret_cast<uint32_t*>(&v);
}
__device__ __forceinline__ void split2(float x, float y, uint32_t& hi, uint32_t& lo) {
    __nv_bfloat16 hx = __float2bfloat16(x), hy = __float2bfloat16(y);
    float rx = x - __bfloat162float(hx);
    float ry = y - __bfloat162float(hy);
    __nv_bfloat162 H; H.x = hx; H.y = hy;
    hi = *reinterpret_cast<uint32_t*>(&H);
    lo = packbf2(rx, ry);
}

__device__ __forceinline__ void mma16816(float* d,
                                         uint32_t a0, uint32_t a1, uint32_t a2, uint32_t a3,
                                         uint32_t b0, uint32_t b1) {
    asm volatile(
        "mma.sync.aligned.m16n8k16.row.col.f32.bf16.bf16.f32 "
        "{%0,%1,%2,%3}, {%4,%5,%6,%7}, {%8,%9}, {%0,%1,%2,%3};"
        : "+f"(d[0]), "+f"(d[1]), "+f"(d[2]), "+f"(d[3])
        : "r"(a0), "r"(a1), "r"(a2), "r"(a3), "r"(b0), "r"(b1));
}

// one k16 step: 18 MMAs over 6 accumulators, round-robin (acc revisit distance 6)
__device__ __forceinline__ void mma_step6(float acc[2][3][4],
                                          const uint4& ah, const uint4& al,
                                          const uint4 b[6]) {
    // hi x hi
    mma16816(acc[0][0], ah.x, ah.y, ah.z, ah.w, b[0].x, b[0].y);
    mma16816(acc[0][1], ah.x, ah.y, ah.z, ah.w, b[2].x, b[2].y);
    mma16816(acc[0][2], ah.x, ah.y, ah.z, ah.w, b[4].x, b[4].y);
    mma16816(acc[1][0], ah.x, ah.y, ah.z, ah.w, b[1].x, b[1].y);
    mma16816(acc[1][1], ah.x, ah.y, ah.z, ah.w, b[3].x, b[3].y);
    mma16816(acc[1][2], ah.x, ah.y, ah.z, ah.w, b[5].x, b[5].y);
    // hi x lo
    mma16816(acc[0][0], ah.x, ah.y, ah.z, ah.w, b[0].z, b[0].w);
    mma16816(acc[0][1], ah.x, ah.y, ah.z, ah.w, b[2].z, b[2].w);
    mma16816(acc[0][2], ah.x, ah.y, ah.z, ah.w, b[4].z, b[4].w);
    mma16816(acc[1][0], ah.x, ah.y, ah.z, ah.w, b[1].z, b[1].w);
    mma16816(acc[1][1], ah.x, ah.y, ah.z, ah.w, b[3].z, b[3].w);
    mma16816(acc[1][2], ah.x, ah.y, ah.z, ah.w, b[5].z, b[5].w);
    // lo x hi
    mma16816(acc[0][0], al.x, al.y, al.z, al.w, b[0].x, b[0].y);
    mma16816(acc[0][1], al.x, al.y, al.z, al.w, b[2].x, b[2].y);
    mma16816(acc[0][2], al.x, al.y, al.z, al.w, b[4].x, b[4].y);
    mma16816(acc[1][0], al.x, al.y, al.z, al.w, b[1].x, b[1].y);
    mma16816(acc[1][1], al.x, al.y, al.z, al.w, b[3].x, b[3].y);
    mma16816(acc[1][2], al.x, al.y, al.z, al.w, b[5].x, b[5].y);
}

// ---------------- misc small kernels --------------------------------------------
__global__ void k_init_idx(int* ridx, int* midx) {
    int i = threadIdx.x;
    if (i < NB) { ridx[i] = RHYN - 1; midx[i] = MELN - 1; }
}

__global__ void k_mv(const float* __restrict__ x, int K,
                     const float* __restrict__ W, int ldw, int off,
                     const float* __restrict__ bias, int N,
                     float* __restrict__ out, int act)
{
    __shared__ float xs[128];
    int b = blockIdx.y;
    if (threadIdx.x < K) xs[threadIdx.x] = x[b * K + threadIdx.x];
    __syncthreads();
    int n = blockIdx.x * 256 + threadIdx.x;
    if (n >= N) return;
    float acc = bias[n];
    const float* wr = W + (size_t)n * ldw + off;
#pragma unroll 8
    for (int k = 0; k < K; k++) acc += xs[k] * wr[k];
    if (act) acc = tanh_f(acc);
    out[b * N + n] = acc;
}

// ---------------- weight packer: W[6144,2048] fp32 -> fragment-linear hi/lo ------
__global__ void k_pack(const float* __restrict__ W, uint4* __restrict__ out)
{
    int id = blockIdx.x * 256 + threadIdx.x;
    int l = id & 31;
    int nt = id >> 12;
    int P = nt * 8 + (l >> 2);
    int jt = P / 48, rem = P % 48;
    int g = rem >> 4, c = rem & 15;
    int k16 = (id >> 5) & 127;
    const float* wr = W + (size_t)(g * Hd + jt * 16 + c) * Hd + k16 * 16 + 2 * (l & 3);
    float x0 = wr[0], x1 = wr[1], x8 = wr[8], x9 = wr[9];
    uint32_t h01, l01, h89, l89;
    split2(x0, x1, h01, l01);
    split2(x8, x9, h89, l89);
    out[id] = make_uint4(h01, h89, l01, l89);
}

// ---------------- H fp32 -> fragment-layout hi/lo --------------------------------
__global__ void k_h2frag(const float* __restrict__ H, uint32_t* __restrict__ Af)
{
    int id = blockIdx.x * 256 + threadIdx.x;
    int l = id & 31;
    int k16 = (id >> 5) & 127;
    int mt = id >> 12;
    int m0 = mt * 16 + (l >> 2);
    int k0 = k16 * 16 + 2 * (l & 3);
    const float* r0 = H + (size_t)m0 * Hd + k0;
    const float* r1 = H + (size_t)(m0 + 8) * Hd + k0;
    uint32_t* o = Af + (size_t)id * 8;
    uint32_t hi, lo;
    split2(r0[0], r0[1], hi, lo); o[0] = hi; o[4] = lo;
    split2(r1[0], r1[1], hi, lo); o[1] = hi; o[5] = lo;
    split2(r0[8], r0[9], hi, lo); o[2] = hi; o[6] = lo;
    split2(r1[8], r1[9], hi, lo); o[3] = hi; o[7] = lo;
}

// ---------------- tensor-core GEMM + fused GRU epilogue --------------------------
// grid = 128 (jt), block = 512 (16 warps = 4 m-tiles x 4 k-quarters).
// Each warp computes all 16 n-columns of its m-tile for its k-quarter.
__global__ __launch_bounds__(512, 1)
void k_gemm(const uint4* __restrict__ Bpk,
            const uint32_t* __restrict__ Af,
            const float* __restrict__ Hfp,
            const float* __restrict__ bias,
            const float* __restrict__ gi,
            const float* __restrict__ Woh, int ldw_oh,
            const int* __restrict__ idx,
            float* __restrict__ outH,
            uint32_t* __restrict__ outFrag,
            int plain)
{
    __shared__ float sred[3][4][32][24];
    int jt = blockIdx.x;
    int w = threadIdx.x >> 5, l = threadIdx.x & 31;
    int mt = w & 3;          // m tile
    int kh = w >> 2;         // k quarter
    const int KH = K16N / 4; // 32

    float acc[2][3][4];
#pragma unroll
    for (int n = 0; n < 2; n++)
#pragma unroll
        for (int g = 0; g < 3; g++)
#pragma unroll
            for (int i = 0; i < 4; i++) acc[n][g][i] = 0.0f;

    const uint4* bp[6];
#pragma unroll
    for (int s = 0; s < 6; s++)
        bp[s] = Bpk + ((size_t)(jt * 6 + s) * K16N + kh * KH) * 32 + l;
    const uint32_t* ap = Af + (((size_t)mt * K16N + kh * KH) * 32 + l) * 8;

    uint4 ah = *(const uint4*)ap;
    uint4 al = *(const uint4*)(ap + 4);
    uint4 bc[6];
#pragma unroll
    for (int s = 0; s < 6; s++) bc[s] = *bp[s];

    for (int k16 = 0; k16 < KH - 1; k16++) {
        ap += 256;
        uint4 ah2 = *(const uint4*)ap;
        uint4 al2 = *(const uint4*)(ap + 4);
        uint4 bn[6];
#pragma unroll
        for (int s = 0; s < 6; s++) { bp[s] += 32; bn[s] = *bp[s]; }
        mma_step6(acc, ah, al, bc);
        ah = ah2; al = al2;
#pragma unroll
        for (int s = 0; s < 6; s++) bc[s] = bn[s];
    }
    mma_step6(acc, ah, al, bc);

    // combine k-quarters: warps kh=1..3 dump, kh=0 adds + epilogue
    if (kh) {
#pragma unroll
        for (int n = 0; n < 2; n++)
#pragma unroll
            for (int g = 0; g < 3; g++)
#pragma unroll
                for (int i = 0; i < 4; i++)
                    sred[kh - 1][mt][l][(n * 3 + g) * 4 + i] = acc[n][g][i];
    }
    __syncthreads();
    if (kh) return;
#pragma unroll
    for (int s = 0; s < 3; s++)
#pragma unroll
        for (int n = 0; n < 2; n++)
#pragma unroll
            for (int g = 0; g < 3; g++)
#pragma unroll
                for (int i = 0; i < 4; i++)
                    acc[n][g][i] += sred[s][mt][l][(n * 3 + g) * 4 + i];

    // D mapping per nh: acc[nh][g][0]=(m0,c0) [1]=(m0,c1) [2]=(m1,c0) [3]=(m1,c1)
    int q = l >> 2, tp = l & 3;
    int m0 = mt * 16 + q, m1 = m0 + 8;

    if (plain) {
#pragma unroll
        for (int nh = 0; nh < 2; nh++) {
            int c0 = jt * 16 + nh * 8 + 2 * tp, c1 = c0 + 1;
#pragma unroll
            for (int g = 0; g < 3; g++) {
                float bb0 = bias[g * Hd + c0], bb1 = bias[g * Hd + c1];
                outH[(size_t)m0 * G3 + g * Hd + c0] = acc[nh][g][0] + bb0;
                outH[(size_t)m0 * G3 + g * Hd + c1] = acc[nh][g][1] + bb1;
                outH[(size_t)m1 * G3 + g * Hd + c0] = acc[nh][g][2] + bb0;
                outH[(size_t)m1 * G3 + g * Hd + c1] = acc[nh][g][3] + bb1;
            }
        }
        return;
    }

    int ix0 = 0, ix1 = 0;
    if (Woh) { ix0 = idx[m0]; ix1 = idx[m1]; }
    int lp = q * 4 + tp;
    uint32_t* fb = outFrag + (((size_t)mt * K16N + jt) * 32 + lp) * 8;

#pragma unroll
    for (int nh = 0; nh < 2; nh++) {
        int c0 = jt * 16 + nh * 8 + 2 * tp, c1 = c0 + 1;
        float br = bias[c0], brX = bias[c1];
        float bz = bias[Hd + c0], bzX = bias[Hd + c1];
        float bn = bias[2 * Hd + c0], bnX = bias[2 * Hd + c1];

        float hout[4];
#pragma unroll
        for (int v = 0; v < 4; v++) {
            int b = (v & 2) ? m1 : m0;
            int c = (v & 1) ? c1 : c0;
            float gir = gi[(size_t)b * G3 + c];
            float giz = gi[(size_t)b * G3 + Hd + c];
            float gin = gi[(size_t)b * G3 + 2 * Hd + c];
            if (Woh) {
                int ix = (v & 2) ? ix1 : ix0;
                gir += Woh[(size_t)c * ldw_oh + ix];
                giz += Woh[(size_t)(Hd + c) * ldw_oh + ix];
                gin += Woh[(size_t)(2 * Hd + c) * ldw_oh + ix];
            }
            float ghr = acc[nh][0][v] + ((v & 1) ? brX : br);
            float ghz = acc[nh][1][v] + ((v & 1) ? bzX : bz);
            float ghn = acc[nh][2][v] + ((v & 1) ? bnX : bn);
            float r = sigm_f(gir + ghr);
            float u = sigm_f(giz + ghz);
            float n = tanh_f(gin + r * ghn);
            float hp = Hfp[(size_t)b * Hd + c];
            hout[v] = (1.0f - u) * n + u * hp;
            outH[(size_t)b * Hd + c] = hout[v];
        }

        uint32_t hi0, lo0, hi1, lo1;
        split2(hout[0], hout[1], hi0, lo0);
        split2(hout[2], hout[3], hi1, lo1);
        fb[nh * 2 + 0] = hi0;
        fb[nh * 2 + 1] = hi1;
        fb[4 + nh * 2 + 0] = lo0;
        fb[4 + nh * 2 + 1] = lo1;
    }
}

// ---------------- rhythm logits + log_softmax + argmax ---------------------------
__global__ void k_rhylog(const float* __restrict__ Hn, const float* __restrict__ wo0,
                         const float* __restrict__ bo0,
                         float* __restrict__ rlo, int* __restrict__ ridx)
{
    int b = blockIdx.x, tid = threadIdx.x;
    float p0 = 0.f, p1 = 0.f, p2 = 0.f;
    for (int k = tid; k < Hd; k += 128) {
        float h = Hn[(size_t)b * Hd + k];
        p0 += h * wo0[k];
        p1 += h * wo0[Hd + k];
        p2 += h * wo0[2 * Hd + k];
    }
    __shared__ float s0[128], s1[128], s2[128];
    s0[tid] = p0; s1[tid] = p1; s2[tid] = p2;
    __syncthreads();
    for (int off = 64; off > 0; off >>= 1) {
        if (tid < off) {
            s0[tid] += s0[tid + off];
            s1[tid] += s1[tid + off];
            s2[tid] += s2[tid + off];
        }
        __syncthreads();
    }
    if (tid == 0) {
        float l0 = s0[0] + bo0[0], l1 = s1[0] + bo0[1], l2 = s2[0] + bo0[2];
        float m = fmaxf(l0, fmaxf(l1, l2));
        float z = m + logf(expf(l0 - m) + expf(l1 - m) + expf(l2 - m));
        rlo[b * 3 + 0] = l0 - z;
        rlo[b * 3 + 1] = l1 - z;
        rlo[b * 3 + 2] = l2 - z;
        int ix = 0; float bv = l0;
        if (l1 > bv) { bv = l1; ix = 1; }
        if (l2 > bv) { bv = l2; ix = 2; }
        ridx[b] = ix;
    }
}

// ---------------- build gi1t[t][b][:] -------------------------------------------
__global__ void k_gi1t(const float* __restrict__ gi1z,
                       const float* __restrict__ cond,
                       const float* __restrict__ rlo,
                       const float* __restrict__ w_ih1,
                       float* __restrict__ gi1t)
{
    int n = blockIdx.x * 256 + threadIdx.x;
    int t = blockIdx.y;
    float wr[RHYN], wc[CHN];
#pragma unroll
    for (int j = 0; j < RHYN; j++) wr[j] = w_ih1[(size_t)n * 273 + MELN + j];
#pragma unroll
    for (int j = 0; j < CHN; j++) wc[j] = w_ih1[(size_t)n * 273 + MELN + RHYN + 128 + j];
    for (int b = 0; b < NB; b++) {
        float s = gi1z[(size_t)b * G3 + n];
        const float* r = &rlo[(t * NB + b) * RHYN];
        s += r[0] * wr[0] + r[1] * wr[1] + r[2] * wr[2];
        const float* c = &cond[(b * TT + t) * CHN];
#pragma unroll
        for (int j = 0; j < CHN; j++) s += c[j] * wc[j];
        gi1t[((size_t)t * NB + b) * G3 + n] = s;
    }
}

// ---------------- melody logits + log_softmax + argmax + output ------------------
__global__ void k_mellog(const float* __restrict__ Hn, const float* __restrict__ wo1,
                         const float* __restrict__ bo1,
                         float* __restrict__ outmel, int t, int* __restrict__ midx)
{
    __shared__ __align__(16) float hs[Hd];
    __shared__ float ls[MELN];
    __shared__ float red[256];
    int b = blockIdx.x, tid = threadIdx.x;
    int w = tid >> 5, l = tid & 31;
    for (int k = tid; k < Hd; k += 256) hs[k] = Hn[(size_t)b * Hd + k];
    __syncthreads();
    const float4* h4 = (const float4*)hs;
    for (int r = w; r < MELN; r += 8) {
        const float4* w4 = (const float4*)(wo1 + (size_t)r * Hd);
        float s = 0.f;
#pragma unroll
        for (int c = l; c < Hd / 4; c += 32) {
            float4 a = h4[c], q = w4[c];
            s += a.x * q.x + a.y * q.y + a.z * q.z + a.w * q.w;
        }
#pragma unroll
        for (int off = 16; off > 0; off >>= 1) s += __shfl_xor_sync(0xffffffffu, s, off);
        if (l == 0) ls[r] = s + bo1[r];
    }
    __syncthreads();
    red[tid] = (tid < MELN) ? ls[tid] : -3.4e38f;
    __syncthreads();
    for (int off = 128; off > 0; off >>= 1) {
        if (tid < off) red[tid] = fmaxf(red[tid], red[tid + off]);
        __syncthreads();
    }
    float m = red[0];
    __syncthreads();
    red[tid] = (tid < MELN) ? expf(ls[tid] - m) : 0.f;
    __syncthreads();
    for (int off = 128; off > 0; off >>= 1) {
        if (tid < off) red[tid] += red[tid + off];
        __syncthreads();
    }
    float z = m + logf(red[0]);
    if (tid < MELN)
        outmel[((size_t)b * TT + t) * MELN + tid] = ls[tid] - z;
    if (tid == 0) {
        int ix = 0; float bv = ls[0];
        for (int c = 1; c < MELN; c++) if (ls[c] > bv) { bv = ls[c]; ix = c; }
        midx[b] = ix;
    }
}

// ---------------- host driver ----------------------------------------------------
extern "C" void kernel_launch(void* const* d_in, const int* in_sizes, int n_in,
                              void* d_out, int out_size)
{
    const float* z1    = (const float*)d_in[0];
    const float* z2    = (const float*)d_in[1];
    const float* cond  = (const float*)d_in[2];
    const float* w_ih0 = (const float*)d_in[3];
    const float* w_hh0 = (const float*)d_in[4];
    const float* b_ih0 = (const float*)d_in[5];
    const float* b_hh0 = (const float*)d_in[6];
    const float* w_ih1 = (const float*)d_in[7];
    const float* w_hh1 = (const float*)d_in[8];
    const float* b_ih1 = (const float*)d_in[9];
    const float* b_hh1 = (const float*)d_in[10];
    const float* w_ih2 = (const float*)d_in[11];
    const float* w_hh2 = (const float*)d_in[12];
    const float* b_ih2 = (const float*)d_in[13];
    const float* b_hh2 = (const float*)d_in[14];
    const float* wi0   = (const float*)d_in[15];
    const float* bi0   = (const float*)d_in[16];
    const float* wo0   = (const float*)d_in[17];
    const float* bo0   = (const float*)d_in[18];
    const float* wi1   = (const float*)d_in[19];
    const float* bi1   = (const float*)d_in[20];
    const float* wo1   = (const float*)d_in[21];
    const float* bo1   = (const float*)d_in[22];
    float* out = (float*)d_out;

    float *hB, *haB, *hbB, *gic0, *gi1z, *gi1t, *gi2, *rlo;
    int *ridx, *midx;
    uint4 *Bp0, *Bp1, *Bp2i, *Bp2h;
    uint32_t *hfr, *hafr, *hbfr;
    cudaGetSymbolAddress((void**)&hB,   g_h);
    cudaGetSymbolAddress((void**)&haB,  g_ha);
    cudaGetSymbolAddress((void**)&hbB,  g_hb);
    cudaGetSymbolAddress((void**)&gic0, g_gic0);
    cudaGetSymbolAddress((void**)&gi1z, g_gi1z);
    cudaGetSymbolAddress((void**)&gi1t, g_gi1t);
    cudaGetSymbolAddress((void**)&gi2,  g_gi2);
    cudaGetSymbolAddress((void**)&rlo,  g_rlo);
    cudaGetSymbolAddress((void**)&ridx, g_ridx);
    cudaGetSymbolAddress((void**)&midx, g_midx);
    cudaGetSymbolAddress((void**)&Bp0,  g_Bp0);
    cudaGetSymbolAddress((void**)&Bp1,  g_Bp1);
    cudaGetSymbolAddress((void**)&Bp2i, g_Bp2i);
    cudaGetSymbolAddress((void**)&Bp2h, g_Bp2h);
    cudaGetSymbolAddress((void**)&hfr,  g_hfrag);
    cudaGetSymbolAddress((void**)&hafr, g_hafrag);
    cudaGetSymbolAddress((void**)&hbfr, g_hbfrag);

    float* hbuf[2]  = { hB,  hB  + NB * Hd };
    float* habuf[2] = { haB, haB + NB * Hd };
    float* hbbuf[2] = { hbB, hbB + NB * Hd };
    uint32_t* hfrag[2]  = { hfr,  hfr  + FRAGU32 };
    uint32_t* hafrag[2] = { hafr, hafr + FRAGU32 };
    uint32_t* hbfrag[2] = { hbfr, hbfr + FRAGU32 };

    k_init_idx<<<1, 64>>>(ridx, midx);

    k_pack<<<BPKSZ / 256, 256>>>(w_hh0, Bp0);
    k_pack<<<BPKSZ / 256, 256>>>(w_hh1, Bp1);
    k_pack<<<BPKSZ / 256, 256>>>(w_ih2, Bp2i);
    k_pack<<<BPKSZ / 256, 256>>>(w_hh2, Bp2h);

    k_mv<<<dim3(Hd / 256, NB), 256>>>(z2, 128, wi0, 128, 0, bi0, Hd, hbuf[0], 1);
    k_mv<<<dim3(Hd / 256, NB), 256>>>(z1, 128, wi1, 128, 0, bi1, Hd, habuf[0], 1);
    k_mv<<<dim3(G3 / 256, NB), 256>>>(z2, 128, w_ih0, 131, RHYN, b_ih0, G3, gic0, 0);
    k_mv<<<dim3(G3 / 256, NB), 256>>>(z1, 128, w_ih1, 273, MELN + RHYN, b_ih1, G3, gi1z, 0);
    k_h2frag<<<64, 256>>>(hbuf[0], hfrag[0]);
    k_h2frag<<<64, 256>>>(habuf[0], hafrag[0]);

    // ---- rhythm phase ----
    for (int t = 0; t < TT; t++) {
        k_gemm<<<128, 512>>>(Bp0, hfrag[t & 1], hbuf[t & 1], b_hh0, gic0,
                             w_ih0, 131, ridx + t * NB,
                             hbuf[(t + 1) & 1], hfrag[(t + 1) & 1], 0);
        k_rhylog<<<NB, 128>>>(hbuf[(t + 1) & 1], wo0, bo0,
                              rlo + t * NB * RHYN, ridx + (t + 1) * NB);
    }

    // ---- per-step gi for melody GRU1 ----
    k_gi1t<<<dim3(G3 / 256, TT), 256>>>(gi1z, cond, rlo, w_ih1, gi1t);

    // ---- melody phase ----
    for (int t = 0; t < TT; t++) {
        k_gemm<<<128, 512>>>(Bp1, hafrag[t & 1], habuf[t & 1], b_hh1,
                             gi1t + (size_t)t * NB * G3,
                             w_ih1, 273, midx + t * NB,
                             habuf[(t + 1) & 1], hafrag[(t + 1) & 1], 0);
        k_gemm<<<128, 512>>>(Bp2i, hafrag[(t + 1) & 1], nullptr, b_ih2,
                             nullptr, nullptr, 0, nullptr,
                             gi2, nullptr, 1);
        const uint32_t* fIn = (t == 0) ? hafrag[1] : hbfrag[t & 1];
        const float* fpIn   = (t == 0) ? habuf[1]  : hbbuf[t & 1];
        k_gemm<<<128, 512>>>(Bp2h, fIn, fpIn, b_hh2, gi2,
                             nullptr, 0, nullptr,
                             hbbuf[(t + 1) & 1], hbfrag[(t + 1) & 1], 0);
        k_mellog<<<NB, 256>>>(hbbuf[(t + 1) & 1], wo1, bo1, out, t, midx + (t + 1) * NB);
    }
}

// round 7
// speedup vs baseline: 3.2461x; 1.0200x over previous
#include <cuda_runtime.h>
#include <cuda_bf16.h>
#include <math.h>
#include <stdint.h>
#include <stddef.h>

#define NB   64
#define Hd   2048
#define G3   6144
#define TT   32
#define MELN 130
#define CHN  12
#define RHYN 3
#define NTILE 768          // G3/8
#define K16N  128          // Hd/16
#define FRAGU32 (4*K16N*32*8)   // 131072 u32 per H operand
#define BPKSZ (NTILE*K16N*32)   // uint4 count per packed weight matrix
#define SST (K16N*32)           // uint4 stride between B streams

// ---------------- device scratch ------------------------------------------------
__device__ float g_h[2 * NB * Hd];
__device__ float g_ha[2 * NB * Hd];
__device__ float g_hb[2 * NB * Hd];
__device__ float g_gic0[NB * G3];
__device__ float g_gi1z[NB * G3];
__device__ float g_gi1t[(size_t)TT * NB * G3];
__device__ float g_gi2[NB * G3];
__device__ float g_rlo[TT * NB * RHYN];
__device__ int   g_ridx[(TT + 1) * NB];
__device__ int   g_midx[(TT + 1) * NB];

__device__ uint4 g_Bp0[BPKSZ];    // packed w_hh0 (hi/lo)
__device__ uint4 g_Bp1[BPKSZ];    // packed w_hh1
__device__ uint4 g_Bp2i[BPKSZ];   // packed w_ih2
__device__ uint4 g_Bp2h[BPKSZ];   // packed w_hh2

__device__ uint32_t g_hfrag[2][FRAGU32];
__device__ uint32_t g_hafrag[2][FRAGU32];
__device__ uint32_t g_hbfrag[2][FRAGU32];

// accurate-even-under-fast-math activations
__device__ __forceinline__ float sigm_f(float x) { return 1.0f / (1.0f + expf(-x)); }
__device__ __forceinline__ float tanh_f(float x) { return 1.0f - 2.0f / (expf(2.0f * x) + 1.0f); }

__device__ __forceinline__ uint32_t packbf2(float x, float y) {
    __nv_bfloat162 v = __floats2bfloat162_rn(x, y);
    return *reinterpret_cast<uint32_t*>(&v);
}
__device__ __forceinline__ void split2(float x, float y, uint32_t& hi, uint32_t& lo) {
    __nv_bfloat16 hx = __float2bfloat16(x), hy = __float2bfloat16(y);
    float rx = x - __bfloat162float(hx);
    float ry = y - __bfloat162float(hy);
    __nv_bfloat162 H; H.x = hx; H.y = hy;
    hi = *reinterpret_cast<uint32_t*>(&H);
    lo = packbf2(rx, ry);
}

__device__ __forceinline__ void mma16816(float* d,
                                         uint32_t a0, uint32_t a1, uint32_t a2, uint32_t a3,
                                         uint32_t b0, uint32_t b1) {
    asm volatile(
        "mma.sync.aligned.m16n8k16.row.col.f32.bf16.bf16.f32 "
        "{%0,%1,%2,%3}, {%4,%5,%6,%7}, {%8,%9}, {%0,%1,%2,%3};"
        : "+f"(d[0]), "+f"(d[1]), "+f"(d[2]), "+f"(d[3])
        : "r"(a0), "r"(a1), "r"(a2), "r"(a3), "r"(b0), "r"(b1));
}

// one k16 step: 18 MMAs over 6 accumulators, round-robin (acc revisit distance 6)
__device__ __forceinline__ void mma_step6(float acc[2][3][4],
                                          const uint4& ah, const uint4& al,
                                          const uint4 b[6]) {
    mma16816(acc[0][0], ah.x, ah.y, ah.z, ah.w, b[0].x, b[0].y);
    mma16816(acc[0][1], ah.x, ah.y, ah.z, ah.w, b[2].x, b[2].y);
    mma16816(acc[0][2], ah.x, ah.y, ah.z, ah.w, b[4].x, b[4].y);
    mma16816(acc[1][0], ah.x, ah.y, ah.z, ah.w, b[1].x, b[1].y);
    mma16816(acc[1][1], ah.x, ah.y, ah.z, ah.w, b[3].x, b[3].y);
    mma16816(acc[1][2], ah.x, ah.y, ah.z, ah.w, b[5].x, b[5].y);
    mma16816(acc[0][0], ah.x, ah.y, ah.z, ah.w, b[0].z, b[0].w);
    mma16816(acc[0][1], ah.x, ah.y, ah.z, ah.w, b[2].z, b[2].w);
    mma16816(acc[0][2], ah.x, ah.y, ah.z, ah.w, b[4].z, b[4].w);
    mma16816(acc[1][0], ah.x, ah.y, ah.z, ah.w, b[1].z, b[1].w);
    mma16816(acc[1][1], ah.x, ah.y, ah.z, ah.w, b[3].z, b[3].w);
    mma16816(acc[1][2], ah.x, ah.y, ah.z, ah.w, b[5].z, b[5].w);
    mma16816(acc[0][0], al.x, al.y, al.z, al.w, b[0].x, b[0].y);
    mma16816(acc[0][1], al.x, al.y, al.z, al.w, b[2].x, b[2].y);
    mma16816(acc[0][2], al.x, al.y, al.z, al.w, b[4].x, b[4].y);
    mma16816(acc[1][0], al.x, al.y, al.z, al.w, b[1].x, b[1].y);
    mma16816(acc[1][1], al.x, al.y, al.z, al.w, b[3].x, b[3].y);
    mma16816(acc[1][2], al.x, al.y, al.z, al.w, b[5].x, b[5].y);
}

// ---------------- misc small kernels --------------------------------------------
__global__ void k_init_idx(int* ridx, int* midx) {
    int i = threadIdx.x;
    if (i < NB) { ridx[i] = RHYN - 1; midx[i] = MELN - 1; }
}

__global__ void k_mv(const float* __restrict__ x, int K,
                     const float* __restrict__ W, int ldw, int off,
                     const float* __restrict__ bias, int N,
                     float* __restrict__ out, int act)
{
    __shared__ float xs[128];
    int b = blockIdx.y;
    if (threadIdx.x < K) xs[threadIdx.x] = x[b * K + threadIdx.x];
    __syncthreads();
    int n = blockIdx.x * 256 + threadIdx.x;
    if (n >= N) return;
    float acc = bias[n];
    const float* wr = W + (size_t)n * ldw + off;
#pragma unroll 8
    for (int k = 0; k < K; k++) acc += xs[k] * wr[k];
    if (act) acc = tanh_f(acc);
    out[b * N + n] = acc;
}

// ---------------- weight packer: 4 matrices at once, fragment-linear hi/lo -------
__global__ void k_pack4(const float* __restrict__ W0, const float* __restrict__ W1,
                        const float* __restrict__ W2, const float* __restrict__ W3,
                        uint4* __restrict__ O0, uint4* __restrict__ O1,
                        uint4* __restrict__ O2, uint4* __restrict__ O3)
{
    const float* W; uint4* out;
    switch (blockIdx.y) {
        case 0:  W = W0; out = O0; break;
        case 1:  W = W1; out = O1; break;
        case 2:  W = W2; out = O2; break;
        default: W = W3; out = O3; break;
    }
    int id = blockIdx.x * 256 + threadIdx.x;
    int l = id & 31;
    int nt = id >> 12;
    int P = nt * 8 + (l >> 2);
    int jt = P / 48, rem = P % 48;
    int g = rem >> 4, c = rem & 15;
    int k16 = (id >> 5) & 127;
    const float* wr = W + (size_t)(g * Hd + jt * 16 + c) * Hd + k16 * 16 + 2 * (l & 3);
    float x0 = wr[0], x1 = wr[1], x8 = wr[8], x9 = wr[9];
    uint32_t h01, l01, h89, l89;
    split2(x0, x1, h01, l01);
    split2(x8, x9, h89, l89);
    out[id] = make_uint4(h01, h89, l01, l89);
}

// ---------------- H fp32 -> fragment-layout hi/lo --------------------------------
__global__ void k_h2frag(const float* __restrict__ H, uint32_t* __restrict__ Af)
{
    int id = blockIdx.x * 256 + threadIdx.x;
    int l = id & 31;
    int k16 = (id >> 5) & 127;
    int mt = id >> 12;
    int m0 = mt * 16 + (l >> 2);
    int k0 = k16 * 16 + 2 * (l & 3);
    const float* r0 = H + (size_t)m0 * Hd + k0;
    const float* r1 = H + (size_t)(m0 + 8) * Hd + k0;
    uint32_t* o = Af + (size_t)id * 8;
    uint32_t hi, lo;
    split2(r0[0], r0[1], hi, lo); o[0] = hi; o[4] = lo;
    split2(r1[0], r1[1], hi, lo); o[1] = hi; o[5] = lo;
    split2(r0[8], r0[9], hi, lo); o[2] = hi; o[6] = lo;
    split2(r1[8], r1[9], hi, lo); o[3] = hi; o[7] = lo;
}

// ---------------- tensor-core GEMM + fused GRU epilogue --------------------------
// grid = 128 (jt), block = 512 (16 warps = 4 m-tiles x 4 k-quarters).
// 2-stage register double-buffer: loads for k+2/k+3 in flight while k/k+1 compute.
__global__ __launch_bounds__(512, 1)
void k_gemm(const uint4* __restrict__ Bpk,
            const uint32_t* __restrict__ Af,
            const float* __restrict__ Hfp,
            const float* __restrict__ bias,
            const float* __restrict__ gi,
            const float* __restrict__ Woh, int ldw_oh,
            const int* __restrict__ idx,
            float* __restrict__ outH,
            uint32_t* __restrict__ outFrag,
            int plain)
{
    __shared__ float sred[3][4][32][24];
    int jt = blockIdx.x;
    int w = threadIdx.x >> 5, l = threadIdx.x & 31;
    int mt = w & 3;          // m tile
    int kh = w >> 2;         // k quarter
    const int KH = K16N / 4; // 32

    float acc[2][3][4];
#pragma unroll
    for (int n = 0; n < 2; n++)
#pragma unroll
        for (int g = 0; g < 3; g++)
#pragma unroll
            for (int i = 0; i < 4; i++) acc[n][g][i] = 0.0f;

    const uint4* bptr = Bpk + ((size_t)(jt * 6) * K16N + kh * KH) * 32 + l;
    const uint4* ap4 = (const uint4*)(Af + (((size_t)mt * K16N + kh * KH) * 32 + l) * 8);

    uint4 A0h, A0l, A1h, A1l, B0[6], B1[6];
    A0h = ap4[0];  A0l = ap4[1];
    A1h = ap4[64]; A1l = ap4[65];
#pragma unroll
    for (int s = 0; s < 6; s++) { B0[s] = bptr[s * SST]; B1[s] = bptr[s * SST + 32]; }

#pragma unroll 1
    for (int k16 = 0; k16 < KH - 2; k16 += 2) {
        mma_step6(acc, A0h, A0l, B0);
        ap4 += 128; bptr += 64;                       // advance two k-steps
        A0h = ap4[0]; A0l = ap4[1];
#pragma unroll
        for (int s = 0; s < 6; s++) B0[s] = bptr[s * SST];
        mma_step6(acc, A1h, A1l, B1);
        A1h = ap4[64]; A1l = ap4[65];
#pragma unroll
        for (int s = 0; s < 6; s++) B1[s] = bptr[s * SST + 32];
    }
    mma_step6(acc, A0h, A0l, B0);
    mma_step6(acc, A1h, A1l, B1);

    // combine k-quarters: warps kh=1..3 dump, kh=0 adds + epilogue
    if (kh) {
#pragma unroll
        for (int n = 0; n < 2; n++)
#pragma unroll
            for (int g = 0; g < 3; g++)
#pragma unroll
                for (int i = 0; i < 4; i++)
                    sred[kh - 1][mt][l][(n * 3 + g) * 4 + i] = acc[n][g][i];
    }
    __syncthreads();
    if (kh) return;
#pragma unroll
    for (int s = 0; s < 3; s++)
#pragma unroll
        for (int n = 0; n < 2; n++)
#pragma unroll
            for (int g = 0; g < 3; g++)
#pragma unroll
                for (int i = 0; i < 4; i++)
                    acc[n][g][i] += sred[s][mt][l][(n * 3 + g) * 4 + i];

    // D mapping per nh: acc[nh][g][0]=(m0,c0) [1]=(m0,c1) [2]=(m1,c0) [3]=(m1,c1)
    int q = l >> 2, tp = l & 3;
    int m0 = mt * 16 + q, m1 = m0 + 8;

    if (plain) {
#pragma unroll
        for (int nh = 0; nh < 2; nh++) {
            int c0 = jt * 16 + nh * 8 + 2 * tp, c1 = c0 + 1;
#pragma unroll
            for (int g = 0; g < 3; g++) {
                float bb0 = bias[g * Hd + c0], bb1 = bias[g * Hd + c1];
                outH[(size_t)m0 * G3 + g * Hd + c0] = acc[nh][g][0] + bb0;
                outH[(size_t)m0 * G3 + g * Hd + c1] = acc[nh][g][1] + bb1;
                outH[(size_t)m1 * G3 + g * Hd + c0] = acc[nh][g][2] + bb0;
                outH[(size_t)m1 * G3 + g * Hd + c1] = acc[nh][g][3] + bb1;
            }
        }
        return;
    }

    int ix0 = 0, ix1 = 0;
    if (Woh) { ix0 = idx[m0]; ix1 = idx[m1]; }
    int lp = q * 4 + tp;
    uint32_t* fb = outFrag + (((size_t)mt * K16N + jt) * 32 + lp) * 8;

#pragma unroll
    for (int nh = 0; nh < 2; nh++) {
        int c0 = jt * 16 + nh * 8 + 2 * tp, c1 = c0 + 1;
        float br = bias[c0], brX = bias[c1];
        float bz = bias[Hd + c0], bzX = bias[Hd + c1];
        float bn = bias[2 * Hd + c0], bnX = bias[2 * Hd + c1];

        float hout[4];
#pragma unroll
        for (int v = 0; v < 4; v++) {
            int b = (v & 2) ? m1 : m0;
            int c = (v & 1) ? c1 : c0;
            float gir = gi[(size_t)b * G3 + c];
            float giz = gi[(size_t)b * G3 + Hd + c];
            float gin = gi[(size_t)b * G3 + 2 * Hd + c];
            if (Woh) {
                int ix = (v & 2) ? ix1 : ix0;
                gir += Woh[(size_t)c * ldw_oh + ix];
                giz += Woh[(size_t)(Hd + c) * ldw_oh + ix];
                gin += Woh[(size_t)(2 * Hd + c) * ldw_oh + ix];
            }
            float ghr = acc[nh][0][v] + ((v & 1) ? brX : br);
            float ghz = acc[nh][1][v] + ((v & 1) ? bzX : bz);
            float ghn = acc[nh][2][v] + ((v & 1) ? bnX : bn);
            float r = sigm_f(gir + ghr);
            float u = sigm_f(giz + ghz);
            float n = tanh_f(gin + r * ghn);
            float hp = Hfp[(size_t)b * Hd + c];
            hout[v] = (1.0f - u) * n + u * hp;
            outH[(size_t)b * Hd + c] = hout[v];
        }

        uint32_t hi0, lo0, hi1, lo1;
        split2(hout[0], hout[1], hi0, lo0);
        split2(hout[2], hout[3], hi1, lo1);
        fb[nh * 2 + 0] = hi0;
        fb[nh * 2 + 1] = hi1;
        fb[4 + nh * 2 + 0] = lo0;
        fb[4 + nh * 2 + 1] = lo1;
    }
}

// ---------------- rhythm logits + log_softmax + argmax ---------------------------
__global__ void k_rhylog(const float* __restrict__ Hn, const float* __restrict__ wo0,
                         const float* __restrict__ bo0,
                         float* __restrict__ rlo, int* __restrict__ ridx)
{
    int b = blockIdx.x, tid = threadIdx.x;
    float p0 = 0.f, p1 = 0.f, p2 = 0.f;
    for (int k = tid; k < Hd; k += 128) {
        float h = Hn[(size_t)b * Hd + k];
        p0 += h * wo0[k];
        p1 += h * wo0[Hd + k];
        p2 += h * wo0[2 * Hd + k];
    }
    __shared__ float s0[128], s1[128], s2[128];
    s0[tid] = p0; s1[tid] = p1; s2[tid] = p2;
    __syncthreads();
    for (int off = 64; off > 0; off >>= 1) {
        if (tid < off) {
            s0[tid] += s0[tid + off];
            s1[tid] += s1[tid + off];
            s2[tid] += s2[tid + off];
        }
        __syncthreads();
    }
    if (tid == 0) {
        float l0 = s0[0] + bo0[0], l1 = s1[0] + bo0[1], l2 = s2[0] + bo0[2];
        float m = fmaxf(l0, fmaxf(l1, l2));
        float z = m + logf(expf(l0 - m) + expf(l1 - m) + expf(l2 - m));
        rlo[b * 3 + 0] = l0 - z;
        rlo[b * 3 + 1] = l1 - z;
        rlo[b * 3 + 2] = l2 - z;
        int ix = 0; float bv = l0;
        if (l1 > bv) { bv = l1; ix = 1; }
        if (l2 > bv) { bv = l2; ix = 2; }
        ridx[b] = ix;
    }
}

// ---------------- build gi1t[t][b][:] -------------------------------------------
__global__ void k_gi1t(const float* __restrict__ gi1z,
                       const float* __restrict__ cond,
                       const float* __restrict__ rlo,
                       const float* __restrict__ w_ih1,
                       float* __restrict__ gi1t)
{
    int n = blockIdx.x * 256 + threadIdx.x;
    int t = blockIdx.y;
    float wr[RHYN], wc[CHN];
#pragma unroll
    for (int j = 0; j < RHYN; j++) wr[j] = w_ih1[(size_t)n * 273 + MELN + j];
#pragma unroll
    for (int j = 0; j < CHN; j++) wc[j] = w_ih1[(size_t)n * 273 + MELN + RHYN + 128 + j];
    for (int b = 0; b < NB; b++) {
        float s = gi1z[(size_t)b * G3 + n];
        const float* r = &rlo[(t * NB + b) * RHYN];
        s += r[0] * wr[0] + r[1] * wr[1] + r[2] * wr[2];
        const float* c = &cond[(b * TT + t) * CHN];
#pragma unroll
        for (int j = 0; j < CHN; j++) s += c[j] * wc[j];
        gi1t[((size_t)t * NB + b) * G3 + n] = s;
    }
}

// ---------------- melody logits + log_softmax + argmax + output ------------------
__global__ void k_mellog(const float* __restrict__ Hn, const float* __restrict__ wo1,
                         const float* __restrict__ bo1,
                         float* __restrict__ outmel, int t, int* __restrict__ midx)
{
    __shared__ __align__(16) float hs[Hd];
    __shared__ float ls[MELN];
    __shared__ float red[256];
    int b = blockIdx.x, tid = threadIdx.x;
    int w = tid >> 5, l = tid & 31;
    for (int k = tid; k < Hd; k += 256) hs[k] = Hn[(size_t)b * Hd + k];
    __syncthreads();
    const float4* h4 = (const float4*)hs;
    for (int r = w; r < MELN; r += 8) {
        const float4* w4 = (const float4*)(wo1 + (size_t)r * Hd);
        float s = 0.f;
#pragma unroll
        for (int c = l; c < Hd / 4; c += 32) {
            float4 a = h4[c], q = w4[c];
            s += a.x * q.x + a.y * q.y + a.z * q.z + a.w * q.w;
        }
#pragma unroll
        for (int off = 16; off > 0; off >>= 1) s += __shfl_xor_sync(0xffffffffu, s, off);
        if (l == 0) ls[r] = s + bo1[r];
    }
    __syncthreads();
    red[tid] = (tid < MELN) ? ls[tid] : -3.4e38f;
    __syncthreads();
    for (int off = 128; off > 0; off >>= 1) {
        if (tid < off) red[tid] = fmaxf(red[tid], red[tid + off]);
        __syncthreads();
    }
    float m = red[0];
    __syncthreads();
    red[tid] = (tid < MELN) ? expf(ls[tid] - m) : 0.f;
    __syncthreads();
    for (int off = 128; off > 0; off >>= 1) {
        if (tid < off) red[tid] += red[tid + off];
        __syncthreads();
    }
    float z = m + logf(red[0]);
    if (tid < MELN)
        outmel[((size_t)b * TT + t) * MELN + tid] = ls[tid] - z;
    if (tid == 0) {
        int ix = 0; float bv = ls[0];
        for (int c = 1; c < MELN; c++) if (ls[c] > bv) { bv = ls[c]; ix = c; }
        midx[b] = ix;
    }
}

// ---------------- host driver ----------------------------------------------------
extern "C" void kernel_launch(void* const* d_in, const int* in_sizes, int n_in,
                              void* d_out, int out_size)
{
    const float* z1    = (const float*)d_in[0];
    const float* z2    = (const float*)d_in[1];
    const float* cond  = (const float*)d_in[2];
    const float* w_ih0 = (const float*)d_in[3];
    const float* w_hh0 = (const float*)d_in[4];
    const float* b_ih0 = (const float*)d_in[5];
    const float* b_hh0 = (const float*)d_in[6];
    const float* w_ih1 = (const float*)d_in[7];
    const float* w_hh1 = (const float*)d_in[8];
    const float* b_ih1 = (const float*)d_in[9];
    const float* b_hh1 = (const float*)d_in[10];
    const float* w_ih2 = (const float*)d_in[11];
    const float* w_hh2 = (const float*)d_in[12];
    const float* b_ih2 = (const float*)d_in[13];
    const float* b_hh2 = (const float*)d_in[14];
    const float* wi0   = (const float*)d_in[15];
    const float* bi0   = (const float*)d_in[16];
    const float* wo0   = (const float*)d_in[17];
    const float* bo0   = (const float*)d_in[18];
    const float* wi1   = (const float*)d_in[19];
    const float* bi1   = (const float*)d_in[20];
    const float* wo1   = (const float*)d_in[21];
    const float* bo1   = (const float*)d_in[22];
    float* out = (float*)d_out;

    float *hB, *haB, *hbB, *gic0, *gi1z, *gi1t, *gi2, *rlo;
    int *ridx, *midx;
    uint4 *Bp0, *Bp1, *Bp2i, *Bp2h;
    uint32_t *hfr, *hafr, *hbfr;
    cudaGetSymbolAddress((void**)&hB,   g_h);
    cudaGetSymbolAddress((void**)&haB,  g_ha);
    cudaGetSymbolAddress((void**)&hbB,  g_hb);
    cudaGetSymbolAddress((void**)&gic0, g_gic0);
    cudaGetSymbolAddress((void**)&gi1z, g_gi1z);
    cudaGetSymbolAddress((void**)&gi1t, g_gi1t);
    cudaGetSymbolAddress((void**)&gi2,  g_gi2);
    cudaGetSymbolAddress((void**)&rlo,  g_rlo);
    cudaGetSymbolAddress((void**)&ridx, g_ridx);
    cudaGetSymbolAddress((void**)&midx, g_midx);
    cudaGetSymbolAddress((void**)&Bp0,  g_Bp0);
    cudaGetSymbolAddress((void**)&Bp1,  g_Bp1);
    cudaGetSymbolAddress((void**)&Bp2i, g_Bp2i);
    cudaGetSymbolAddress((void**)&Bp2h, g_Bp2h);
    cudaGetSymbolAddress((void**)&hfr,  g_hfrag);
    cudaGetSymbolAddress((void**)&hafr, g_hafrag);
    cudaGetSymbolAddress((void**)&hbfr, g_hbfrag);

    float* hbuf[2]  = { hB,  hB  + NB * Hd };
    float* habuf[2] = { haB, haB + NB * Hd };
    float* hbbuf[2] = { hbB, hbB + NB * Hd };
    uint32_t* hfrag[2]  = { hfr,  hfr  + FRAGU32 };
    uint32_t* hafrag[2] = { hafr, hafr + FRAGU32 };
    uint32_t* hbfrag[2] = { hbfr, hbfr + FRAGU32 };

    k_init_idx<<<1, 64>>>(ridx, midx);

    k_pack4<<<dim3(BPKSZ / 256, 4), 256>>>(w_hh0, w_hh1, w_ih2, w_hh2,
                                           Bp0, Bp1, Bp2i, Bp2h);

    k_mv<<<dim3(Hd / 256, NB), 256>>>(z2, 128, wi0, 128, 0, bi0, Hd, hbuf[0], 1);
    k_mv<<<dim3(Hd / 256, NB), 256>>>(z1, 128, wi1, 128, 0, bi1, Hd, habuf[0], 1);
    k_mv<<<dim3(G3 / 256, NB), 256>>>(z2, 128, w_ih0, 131, RHYN, b_ih0, G3, gic0, 0);
    k_mv<<<dim3(G3 / 256, NB), 256>>>(z1, 128, w_ih1, 273, MELN + RHYN, b_ih1, G3, gi1z, 0);
    k_h2frag<<<64, 256>>>(hbuf[0], hfrag[0]);
    k_h2frag<<<64, 256>>>(habuf[0], hafrag[0]);

    // ---- rhythm phase ----
    for (int t = 0; t < TT; t++) {
        k_gemm<<<128, 512>>>(Bp0, hfrag[t & 1], hbuf[t & 1], b_hh0, gic0,
                             w_ih0, 131, ridx + t * NB,
                             hbuf[(t + 1) & 1], hfrag[(t + 1) & 1], 0);
        k_rhylog<<<NB, 128>>>(hbuf[(t + 1) & 1], wo0, bo0,
                              rlo + t * NB * RHYN, ridx + (t + 1) * NB);
    }

    // ---- per-step gi for melody GRU1 ----
    k_gi1t<<<dim3(G3 / 256, TT), 256>>>(gi1z, cond, rlo, w_ih1, gi1t);

    // ---- melody phase ----
    for (int t = 0; t < TT; t++) {
        k_gemm<<<128, 512>>>(Bp1, hafrag[t & 1], habuf[t & 1], b_hh1,
                             gi1t + (size_t)t * NB * G3,
                             w_ih1, 273, midx + t * NB,
                             habuf[(t + 1) & 1], hafrag[(t + 1) & 1], 0);
        k_gemm<<<128, 512>>>(Bp2i, hafrag[(t + 1) & 1], nullptr, b_ih2,
                             nullptr, nullptr, 0, nullptr,
                             gi2, nullptr, 1);
        const uint32_t* fIn = (t == 0) ? hafrag[1] : hbfrag[t & 1];
        const float* fpIn   = (t == 0) ? habuf[1]  : hbbuf[t & 1];
        k_gemm<<<128, 512>>>(Bp2h, fIn, fpIn, b_hh2, gi2,
                             nullptr, 0, nullptr,
                             hbbuf[(t + 1) & 1], hbfrag[(t + 1) & 1], 0);
        k_mellog<<<NB, 256>>>(hbbuf[(t + 1) & 1], wo1, bo1, out, t, midx + (t + 1) * NB);
    }
}